// round 2
// baseline (speedup 1.0000x reference)
#include <cuda_runtime.h>
#include <math.h>

#define BATCH 4
#define SEQ   2048
#define DMODEL 2048
#define NHEAD 16
#define HDIM  128
#define MROWS (BATCH * SEQ)   // 8192

// Scratch (allocation-free rule: __device__ globals)
__device__ float g_q[(size_t)MROWS * DMODEL];
__device__ float g_k[(size_t)MROWS * DMODEL];
__device__ float g_v[(size_t)MROWS * DMODEL];
__device__ float g_ctx[(size_t)MROWS * DMODEL];

// ---------------------------------------------------------------------------
// SGEMM:  C[M,N] = A[M,K] @ W[N,K]^T + bias[N]
// A row-major [M,K], W row-major [N,K] (torch Linear layout), both k-contiguous.
// 128x128 block tile, BK=8, 256 threads, 8x8 per thread. M,N,K % 128/8 == 0.
// ---------------------------------------------------------------------------
__global__ __launch_bounds__(256) void sgemm_nt(
    const float* __restrict__ A, const float* __restrict__ W,
    const float* __restrict__ bias, float* __restrict__ C,
    int M, int N, int K)
{
    __shared__ float As[8][132];
    __shared__ float Bs[8][132];

    const int tid = threadIdx.x;
    const int tr  = tid >> 4;          // 0..15  (row group)
    const int tc  = tid & 15;          // 0..15  (col group)
    const int lr  = tid >> 1;          // 0..127 (load row)
    const int lk  = (tid & 1) << 2;    // 0 or 4 (load k offset)

    const float* Ap = A + (size_t)(blockIdx.y * 128 + lr) * K + lk;
    const float* Wp = W + (size_t)(blockIdx.x * 128 + lr) * K + lk;

    float acc[8][8];
#pragma unroll
    for (int i = 0; i < 8; i++)
#pragma unroll
        for (int j = 0; j < 8; j++) acc[i][j] = 0.0f;

    for (int k0 = 0; k0 < K; k0 += 8) {
        float4 av = *(const float4*)(Ap + k0);
        float4 wv = *(const float4*)(Wp + k0);
        __syncthreads();
        As[lk + 0][lr] = av.x; As[lk + 1][lr] = av.y;
        As[lk + 2][lr] = av.z; As[lk + 3][lr] = av.w;
        Bs[lk + 0][lr] = wv.x; Bs[lk + 1][lr] = wv.y;
        Bs[lk + 2][lr] = wv.z; Bs[lk + 3][lr] = wv.w;
        __syncthreads();
#pragma unroll
        for (int kk = 0; kk < 8; kk++) {
            float a[8], b[8];
            *(float4*)&a[0] = *(const float4*)&As[kk][tr * 8];
            *(float4*)&a[4] = *(const float4*)&As[kk][tr * 8 + 4];
            *(float4*)&b[0] = *(const float4*)&Bs[kk][tc * 8];
            *(float4*)&b[4] = *(const float4*)&Bs[kk][tc * 8 + 4];
#pragma unroll
            for (int i = 0; i < 8; i++)
#pragma unroll
                for (int j = 0; j < 8; j++)
                    acc[i][j] += a[i] * b[j];
        }
    }

    const float* bp = bias + blockIdx.x * 128 + tc * 8;
    float bv[8];
#pragma unroll
    for (int j = 0; j < 8; j++) bv[j] = bp[j];

#pragma unroll
    for (int i = 0; i < 8; i++) {
        float* Crow = C + (size_t)(blockIdx.y * 128 + tr * 8 + i) * N
                        + blockIdx.x * 128 + tc * 8;
#pragma unroll
        for (int j = 0; j < 8; j += 4) {
            float4 o;
            o.x = acc[i][j + 0] + bv[j + 0];
            o.y = acc[i][j + 1] + bv[j + 1];
            o.z = acc[i][j + 2] + bv[j + 2];
            o.w = acc[i][j + 3] + bv[j + 3];
            *(float4*)(Crow + j) = o;
        }
    }
}

// ---------------------------------------------------------------------------
// Flash attention: Q,K,V in [B*T, DMODEL] layout (head h occupies cols
// h*128..h*128+127). One block = 32 queries of one (b,h). Stream 32-key tiles
// with online softmax. K and V share one smem buffer (static smem < 48KB).
// 256 threads: ty = tid/8 (query row 0..31), tx = tid%8.
//   S stage : thread (ty,tx) computes scores for keys {tx + 8j}, j=0..3
//   PV stage: thread (ty,tx) owns output cols {32g + 4tx .. +3}, g=0..3
// ---------------------------------------------------------------------------
__global__ __launch_bounds__(256) void attn_kernel(
    const float* __restrict__ Q, const float* __restrict__ Kt,
    const float* __restrict__ V, float* __restrict__ O)
{
    __shared__ float Qs[32 * 132];
    __shared__ float KVs[32 * 132];
    __shared__ float Ps[32 * 33];

    const int tid = threadIdx.x;
    const int ty  = tid >> 3;   // 0..31
    const int tx  = tid & 7;    // 0..7
    const int b   = blockIdx.x >> 4;
    const int h   = blockIdx.x & 15;
    const int q0  = blockIdx.y * 32;

    const size_t base = (size_t)b * SEQ * DMODEL + (size_t)h * HDIM;
    const float scale = 0.08838834764831845f;   // 1/sqrt(128)

    // Load Q tile (32 x 128)
#pragma unroll
    for (int i = 0; i < 4; i++) {
        int idx = tid + i * 256;          // 0..1023 float4s
        int r = idx >> 5, c4 = idx & 31;
        *(float4*)&Qs[r * 132 + c4 * 4] =
            *(const float4*)(Q + base + (size_t)(q0 + r) * DMODEL + c4 * 4);
    }

    float m_prev = -INFINITY, lsum = 0.0f;
    float4 og[4];
#pragma unroll
    for (int g = 0; g < 4; g++) og[g] = make_float4(0.f, 0.f, 0.f, 0.f);

    for (int k0 = 0; k0 < SEQ; k0 += 32) {
        __syncthreads();   // prior PV reads of KVs / Ps done
        // Load K tile
#pragma unroll
        for (int i = 0; i < 4; i++) {
            int idx = tid + i * 256;
            int r = idx >> 5, c4 = idx & 31;
            *(float4*)&KVs[r * 132 + c4 * 4] =
                *(const float4*)(Kt + base + (size_t)(k0 + r) * DMODEL + c4 * 4);
        }
        __syncthreads();

        // Scores: 4 keys per thread
        float a0[4], a1[4], a2[4], a3[4];
#pragma unroll
        for (int j = 0; j < 4; j++) { a0[j] = a1[j] = a2[j] = a3[j] = 0.0f; }
        const float* qrow = &Qs[ty * 132];
#pragma unroll 8
        for (int k4 = 0; k4 < 32; k4++) {
            float4 qv = *(const float4*)(qrow + k4 * 4);
#pragma unroll
            for (int j = 0; j < 4; j++) {
                float4 kv = *(const float4*)(&KVs[(tx + 8 * j) * 132 + k4 * 4]);
                a0[j] += qv.x * kv.x; a1[j] += qv.y * kv.y;
                a2[j] += qv.z * kv.z; a3[j] += qv.w * kv.w;
            }
        }
        float sj[4];
#pragma unroll
        for (int j = 0; j < 4; j++)
            sj[j] = (a0[j] + a1[j] + a2[j] + a3[j]) * scale;

        // Row max over this tile (reduce across the 8 tx lanes of row ty)
        float mloc = fmaxf(fmaxf(sj[0], sj[1]), fmaxf(sj[2], sj[3]));
        mloc = fmaxf(mloc, __shfl_xor_sync(0xffffffffu, mloc, 4, 8));
        mloc = fmaxf(mloc, __shfl_xor_sync(0xffffffffu, mloc, 2, 8));
        mloc = fmaxf(mloc, __shfl_xor_sync(0xffffffffu, mloc, 1, 8));
        float m_new = fmaxf(m_prev, mloc);

        float psum = 0.0f;
#pragma unroll
        for (int j = 0; j < 4; j++) {
            float p = __expf(sj[j] - m_new);
            Ps[ty * 33 + tx + 8 * j] = p;
            psum += p;
        }
        psum += __shfl_xor_sync(0xffffffffu, psum, 4, 8);
        psum += __shfl_xor_sync(0xffffffffu, psum, 2, 8);
        psum += __shfl_xor_sync(0xffffffffu, psum, 1, 8);

        float alpha = __expf(m_prev - m_new);
        lsum = lsum * alpha + psum;
        m_prev = m_new;
#pragma unroll
        for (int g = 0; g < 4; g++) {
            og[g].x *= alpha; og[g].y *= alpha;
            og[g].z *= alpha; og[g].w *= alpha;
        }

        __syncthreads();   // all score reads of KVs done
        // Load V tile (reuse KVs)
#pragma unroll
        for (int i = 0; i < 4; i++) {
            int idx = tid + i * 256;
            int r = idx >> 5, c4 = idx & 31;
            *(float4*)&KVs[r * 132 + c4 * 4] =
                *(const float4*)(V + base + (size_t)(k0 + r) * DMODEL + c4 * 4);
        }
        __syncthreads();

        // PV accumulate
        const float* prow = &Ps[ty * 33];
#pragma unroll 4
        for (int s = 0; s < 32; s++) {
            float p = prow[s];
#pragma unroll
            for (int g = 0; g < 4; g++) {
                float4 vv = *(const float4*)(&KVs[s * 132 + g * 32 + tx * 4]);
                og[g].x += p * vv.x; og[g].y += p * vv.y;
                og[g].z += p * vv.z; og[g].w += p * vv.w;
            }
        }
    }

    float inv_l = 1.0f / lsum;
    float* orow = O + base + (size_t)(q0 + ty) * DMODEL;
#pragma unroll
    for (int g = 0; g < 4; g++) {
        float4 r;
        r.x = og[g].x * inv_l; r.y = og[g].y * inv_l;
        r.z = og[g].z * inv_l; r.w = og[g].w * inv_l;
        *(float4*)(orow + g * 32 + tx * 4) = r;
    }
}

// ---------------------------------------------------------------------------
extern "C" void kernel_launch(void* const* d_in, const int* in_sizes, int n_in,
                              void* d_out, int out_size)
{
    const float* x  = (const float*)d_in[0];
    const float* Wq = (const float*)d_in[1];
    const float* bq = (const float*)d_in[2];
    const float* Wk = (const float*)d_in[3];
    const float* bk = (const float*)d_in[4];
    const float* Wv = (const float*)d_in[5];
    const float* bv = (const float*)d_in[6];
    const float* Wo = (const float*)d_in[7];
    const float* bo = (const float*)d_in[8];
    float* out = (float*)d_out;

    float *qp, *kp, *vp, *cp;
    cudaGetSymbolAddress((void**)&qp, g_q);
    cudaGetSymbolAddress((void**)&kp, g_k);
    cudaGetSymbolAddress((void**)&vp, g_v);
    cudaGetSymbolAddress((void**)&cp, g_ctx);

    dim3 gproj(DMODEL / 128, MROWS / 128);   // (16, 64)
    sgemm_nt<<<gproj, 256>>>(x, Wq, bq, qp, MROWS, DMODEL, DMODEL);
    sgemm_nt<<<gproj, 256>>>(x, Wk, bk, kp, MROWS, DMODEL, DMODEL);
    sgemm_nt<<<gproj, 256>>>(x, Wv, bv, vp, MROWS, DMODEL, DMODEL);

    dim3 gattn(BATCH * NHEAD, SEQ / 32);     // (64, 64)
    attn_kernel<<<gattn, 256>>>(qp, kp, vp, cp);

    sgemm_nt<<<gproj, 256>>>(cp, Wo, bo, out, MROWS, DMODEL, DMODEL);
}

// round 4
// speedup vs baseline: 4.6722x; 4.6722x over previous
#include <cuda_runtime.h>
#include <math.h>
#include <stdint.h>

#define BATCH 4
#define SEQ   2048
#define DMODEL 2048
#define NHEAD 16
#define HDIM  128
#define MROWS (BATCH * SEQ)   // 8192

// Scratch (allocation-free rule: __device__ globals)
__device__ float g_q[(size_t)MROWS * DMODEL];
__device__ float g_k[(size_t)MROWS * DMODEL];
__device__ float g_v[(size_t)MROWS * DMODEL];
__device__ float g_ctx[(size_t)MROWS * DMODEL];

// ---------------------------------------------------------------------------
// TF32 helpers
// ---------------------------------------------------------------------------
__device__ __forceinline__ uint32_t f2tf(float x) {
    uint32_t r;
    asm("cvt.rna.tf32.f32 %0, %1;" : "=r"(r) : "f"(x));
    return r;
}

// D += A(16x8 row) * B(8x8 col),  tf32 inputs, fp32 accum
__device__ __forceinline__ void mma8(float* d, const uint32_t* a, const uint32_t* b) {
    asm volatile(
        "mma.sync.aligned.m16n8k8.row.col.f32.tf32.tf32.f32 "
        "{%0,%1,%2,%3}, {%4,%5,%6,%7}, {%8,%9}, {%0,%1,%2,%3};\n"
        : "+f"(d[0]), "+f"(d[1]), "+f"(d[2]), "+f"(d[3])
        : "r"(a[0]), "r"(a[1]), "r"(a[2]), "r"(a[3]),
          "r"(b[0]), "r"(b[1]));
}

// ---------------------------------------------------------------------------
// TF32 GEMM:  C[M,N] = A[M,K] @ W[N,K]^T + bias[N]
// Block tile 128x128, BK=32, 256 threads, warp grid 2(m) x 4(n),
// warp tile 64x32 -> 4 m-tiles x 4 n-tiles of m16n8k8.
// ---------------------------------------------------------------------------
#define ASTR 36   // smem row stride: bank = 4*(l/4)+(l%4) -> permutation

__global__ __launch_bounds__(256, 2) void gemm_tf32(
    const float* __restrict__ A, const float* __restrict__ W,
    const float* __restrict__ bias, float* __restrict__ C,
    int M, int N, int K)
{
    __shared__ uint32_t As[128 * ASTR];
    __shared__ uint32_t Ws[128 * ASTR];

    const int tid = threadIdx.x;
    const int l   = tid & 31;
    const int w   = tid >> 5;
    const int wm  = w >> 2;        // 0..1
    const int wn  = w & 3;         // 0..3
    const int lg  = l >> 2;        // groupID 0..7
    const int lt  = l & 3;         // threadID_in_group 0..3

    const float* Abase = A + (size_t)(blockIdx.y * 128) * K;
    const float* Wbase = W + (size_t)(blockIdx.x * 128) * K;

    float acc[4][4][4];
#pragma unroll
    for (int mi = 0; mi < 4; mi++)
#pragma unroll
        for (int nj = 0; nj < 4; nj++)
#pragma unroll
            for (int r = 0; r < 4; r++) acc[mi][nj][r] = 0.0f;

    for (int k0 = 0; k0 < K; k0 += 32) {
        __syncthreads();
#pragma unroll
        for (int i = 0; i < 4; i++) {
            int idx = tid + i * 256;           // 0..1023
            int r   = idx >> 3;                // 0..127
            int c4  = (idx & 7) * 4;           // 0..28
            float4 av = *(const float4*)(Abase + (size_t)r * K + k0 + c4);
            uint4 ua; ua.x = f2tf(av.x); ua.y = f2tf(av.y);
                      ua.z = f2tf(av.z); ua.w = f2tf(av.w);
            *(uint4*)&As[r * ASTR + c4] = ua;
            float4 wv = *(const float4*)(Wbase + (size_t)r * K + k0 + c4);
            uint4 uw; uw.x = f2tf(wv.x); uw.y = f2tf(wv.y);
                      uw.z = f2tf(wv.z); uw.w = f2tf(wv.w);
            *(uint4*)&Ws[r * ASTR + c4] = uw;
        }
        __syncthreads();

#pragma unroll
        for (int ks = 0; ks < 4; ks++) {
            int kk = ks * 8 + lt;
            uint32_t af[4][4], bf[4][2];
#pragma unroll
            for (int mi = 0; mi < 4; mi++) {
                int r0 = wm * 64 + mi * 16 + lg;
                af[mi][0] = As[r0 * ASTR + kk];
                af[mi][1] = As[(r0 + 8) * ASTR + kk];
                af[mi][2] = As[r0 * ASTR + kk + 4];
                af[mi][3] = As[(r0 + 8) * ASTR + kk + 4];
            }
#pragma unroll
            for (int nj = 0; nj < 4; nj++) {
                int c0 = wn * 32 + nj * 8 + lg;
                bf[nj][0] = Ws[c0 * ASTR + kk];
                bf[nj][1] = Ws[c0 * ASTR + kk + 4];
            }
#pragma unroll
            for (int mi = 0; mi < 4; mi++)
#pragma unroll
                for (int nj = 0; nj < 4; nj++)
                    mma8(acc[mi][nj], af[mi], bf[nj]);
        }
    }

    // Epilogue: d0,d1 -> (r, c),(r, c+1); d2,d3 -> (r+8, c),(r+8, c+1)
#pragma unroll
    for (int mi = 0; mi < 4; mi++) {
        int r = blockIdx.y * 128 + wm * 64 + mi * 16 + lg;
#pragma unroll
        for (int nj = 0; nj < 4; nj++) {
            int c = blockIdx.x * 128 + wn * 32 + nj * 8 + lt * 2;
            float b0 = bias[c], b1 = bias[c + 1];
            float2 o0 = make_float2(acc[mi][nj][0] + b0, acc[mi][nj][1] + b1);
            float2 o1 = make_float2(acc[mi][nj][2] + b0, acc[mi][nj][3] + b1);
            *(float2*)(C + (size_t)r * N + c)       = o0;
            *(float2*)(C + (size_t)(r + 8) * N + c) = o1;
        }
    }
}

// ---------------------------------------------------------------------------
// TF32 flash attention.
// Q-tile 128 x K-tile 64, 256 threads, 8 warps; warp w owns S/O rows
// [w*16, w*16+16) -> softmax is warp-local (shfl over 4 lanes per row).
// S: warp tile 16x64 (8 n-tiles x 16 ksteps); PV: 16x128 (16 n x 8 k).
// P re-fragmented through smem (warp-private rows, no cross-warp hazard).
// Strides: QSTR/KSTR/PSTR == 4 (mod 32)  -> [row][k] frag reads hit bank 4*lg+lt
//          VSTR          == 8 (mod 32)  -> [k][n]  frag reads hit bank 8*lt+lg
// (both permutations -> conflict-free). K and V phases reuse one buffer with
// their own stride; buffer sized for the larger (VSTR).
// ---------------------------------------------------------------------------
#define QT 128
#define KT 64
#define QSTR 132
#define KSTR 132
#define VSTR 136
#define PSTR 68

__global__ __launch_bounds__(256, 1) void attn_tf32(
    const float* __restrict__ Q, const float* __restrict__ K,
    const float* __restrict__ V, float* __restrict__ O)
{
    extern __shared__ uint32_t sm[];
    uint32_t* Qs  = sm;                       // 128 x QSTR
    uint32_t* KVs = Qs + QT * QSTR;           // 64 x VSTR (K then V)
    uint32_t* Ps  = KVs + KT * VSTR;          // 128 x PSTR

    const int tid = threadIdx.x;
    const int l   = tid & 31;
    const int w   = tid >> 5;
    const int lg  = l >> 2;
    const int lt  = l & 3;
    const int b   = blockIdx.x >> 4;
    const int h   = blockIdx.x & 15;
    const int q0  = blockIdx.y * QT;
    const int r0  = w * 16 + lg;              // this thread's "low" S/O row

    const size_t base = (size_t)b * SEQ * DMODEL + (size_t)h * HDIM;
    const float scale = 0.08838834764831845f; // 1/sqrt(128), folded into Q

    // Load + scale + cvt Q tile (128 x 128)
#pragma unroll
    for (int i = 0; i < 16; i++) {
        int idx = tid + i * 256;
        int r = idx >> 5, c4 = (idx & 31) * 4;
        float4 qv = *(const float4*)(Q + base + (size_t)(q0 + r) * DMODEL + c4);
        uint4 u; u.x = f2tf(qv.x * scale); u.y = f2tf(qv.y * scale);
                 u.z = f2tf(qv.z * scale); u.w = f2tf(qv.w * scale);
        *(uint4*)&Qs[r * QSTR + c4] = u;
    }

    float o[16][4];
#pragma unroll
    for (int j = 0; j < 16; j++)
#pragma unroll
        for (int r = 0; r < 4; r++) o[j][r] = 0.0f;
    float m_lo = -INFINITY, m_hi = -INFINITY, l_lo = 0.0f, l_hi = 0.0f;

    for (int k0 = 0; k0 < SEQ; k0 += KT) {
        __syncthreads();                      // prior PV reads of KVs done
        // Load K tile (64 x 128), stride KSTR
#pragma unroll
        for (int i = 0; i < 8; i++) {
            int idx = tid + i * 256;
            int r = idx >> 5, c4 = (idx & 31) * 4;
            float4 kv = *(const float4*)(K + base + (size_t)(k0 + r) * DMODEL + c4);
            uint4 u; u.x = f2tf(kv.x); u.y = f2tf(kv.y);
                     u.z = f2tf(kv.z); u.w = f2tf(kv.w);
            *(uint4*)&KVs[r * KSTR + c4] = u;
        }
        __syncthreads();

        // S = Q_tile @ K_tile^T  (this warp's 16 rows x 64 keys)
        float s[8][4];
#pragma unroll
        for (int j = 0; j < 8; j++)
#pragma unroll
            for (int r = 0; r < 4; r++) s[j][r] = 0.0f;
#pragma unroll
        for (int ks = 0; ks < 16; ks++) {
            int kk = ks * 8 + lt;
            uint32_t af[4];
            af[0] = Qs[r0 * QSTR + kk];
            af[1] = Qs[(r0 + 8) * QSTR + kk];
            af[2] = Qs[r0 * QSTR + kk + 4];
            af[3] = Qs[(r0 + 8) * QSTR + kk + 4];
#pragma unroll
            for (int j = 0; j < 8; j++) {
                int c0 = j * 8 + lg;
                uint32_t bf[2];
                bf[0] = KVs[c0 * KSTR + kk];
                bf[1] = KVs[c0 * KSTR + kk + 4];
                mma8(s[j], af, bf);
            }
        }

        // Online softmax (rows r0 and r0+8; 4 lanes per row)
        float mlo = -INFINITY, mhi = -INFINITY;
#pragma unroll
        for (int j = 0; j < 8; j++) {
            mlo = fmaxf(mlo, fmaxf(s[j][0], s[j][1]));
            mhi = fmaxf(mhi, fmaxf(s[j][2], s[j][3]));
        }
        mlo = fmaxf(mlo, __shfl_xor_sync(0xffffffffu, mlo, 1));
        mlo = fmaxf(mlo, __shfl_xor_sync(0xffffffffu, mlo, 2));
        mhi = fmaxf(mhi, __shfl_xor_sync(0xffffffffu, mhi, 1));
        mhi = fmaxf(mhi, __shfl_xor_sync(0xffffffffu, mhi, 2));
        float mnl = fmaxf(m_lo, mlo), mnh = fmaxf(m_hi, mhi);
        float al = __expf(m_lo - mnl), ah = __expf(m_hi - mnh);

        float pl = 0.0f, ph = 0.0f;
#pragma unroll
        for (int j = 0; j < 8; j++) {
            float p0 = __expf(s[j][0] - mnl);
            float p1 = __expf(s[j][1] - mnl);
            float p2 = __expf(s[j][2] - mnh);
            float p3 = __expf(s[j][3] - mnh);
            pl += p0 + p1; ph += p2 + p3;
            int c = j * 8 + lt * 2;
            Ps[r0 * PSTR + c]           = f2tf(p0);
            Ps[r0 * PSTR + c + 1]       = f2tf(p1);
            Ps[(r0 + 8) * PSTR + c]     = f2tf(p2);
            Ps[(r0 + 8) * PSTR + c + 1] = f2tf(p3);
        }
        pl += __shfl_xor_sync(0xffffffffu, pl, 1);
        pl += __shfl_xor_sync(0xffffffffu, pl, 2);
        ph += __shfl_xor_sync(0xffffffffu, ph, 1);
        ph += __shfl_xor_sync(0xffffffffu, ph, 2);
        l_lo = l_lo * al + pl;
        l_hi = l_hi * ah + ph;
        m_lo = mnl; m_hi = mnh;
#pragma unroll
        for (int j = 0; j < 16; j++) {
            o[j][0] *= al; o[j][1] *= al;
            o[j][2] *= ah; o[j][3] *= ah;
        }

        __syncthreads();                      // all S reads of KVs done
        // Load V tile (reuse KVs buffer), stride VSTR
#pragma unroll
        for (int i = 0; i < 8; i++) {
            int idx = tid + i * 256;
            int r = idx >> 5, c4 = (idx & 31) * 4;
            float4 vv = *(const float4*)(V + base + (size_t)(k0 + r) * DMODEL + c4);
            uint4 u; u.x = f2tf(vv.x); u.y = f2tf(vv.y);
                     u.z = f2tf(vv.z); u.w = f2tf(vv.w);
            *(uint4*)&KVs[r * VSTR + c4] = u;
        }
        __syncthreads();

        // O += P @ V  (16 rows x 128 dims, k over 64 keys)
#pragma unroll
        for (int ks = 0; ks < 8; ks++) {
            int kk = ks * 8 + lt;
            uint32_t af[4];
            af[0] = Ps[r0 * PSTR + kk];
            af[1] = Ps[(r0 + 8) * PSTR + kk];
            af[2] = Ps[r0 * PSTR + kk + 4];
            af[3] = Ps[(r0 + 8) * PSTR + kk + 4];
#pragma unroll
            for (int j = 0; j < 16; j++) {
                int c0 = j * 8 + lg;
                uint32_t bf[2];
                bf[0] = KVs[kk * VSTR + c0];
                bf[1] = KVs[(kk + 4) * VSTR + c0];
                mma8(o[j], af, bf);
            }
        }
    }

    // Normalize and store
    float il = 1.0f / l_lo, ih = 1.0f / l_hi;
    float* orow0 = O + base + (size_t)(q0 + r0) * DMODEL;
    float* orow1 = O + base + (size_t)(q0 + r0 + 8) * DMODEL;
#pragma unroll
    for (int j = 0; j < 16; j++) {
        int c = j * 8 + lt * 2;
        *(float2*)(orow0 + c) = make_float2(o[j][0] * il, o[j][1] * il);
        *(float2*)(orow1 + c) = make_float2(o[j][2] * ih, o[j][3] * ih);
    }
}

// ---------------------------------------------------------------------------
extern "C" void kernel_launch(void* const* d_in, const int* in_sizes, int n_in,
                              void* d_out, int out_size)
{
    const float* x  = (const float*)d_in[0];
    const float* Wq = (const float*)d_in[1];
    const float* bq = (const float*)d_in[2];
    const float* Wk = (const float*)d_in[3];
    const float* bk = (const float*)d_in[4];
    const float* Wv = (const float*)d_in[5];
    const float* bv = (const float*)d_in[6];
    const float* Wo = (const float*)d_in[7];
    const float* bo = (const float*)d_in[8];
    float* out = (float*)d_out;

    float *qp, *kp, *vp, *cp;
    cudaGetSymbolAddress((void**)&qp, g_q);
    cudaGetSymbolAddress((void**)&kp, g_k);
    cudaGetSymbolAddress((void**)&vp, g_v);
    cudaGetSymbolAddress((void**)&cp, g_ctx);

    const int attn_smem = (QT * QSTR + KT * VSTR + QT * PSTR) * 4;  // 137216 B
    cudaFuncSetAttribute(attn_tf32, cudaFuncAttributeMaxDynamicSharedMemorySize,
                         attn_smem);

    dim3 gproj(DMODEL / 128, MROWS / 128);   // (16, 64)
    gemm_tf32<<<gproj, 256>>>(x, Wq, bq, qp, MROWS, DMODEL, DMODEL);
    gemm_tf32<<<gproj, 256>>>(x, Wk, bk, kp, MROWS, DMODEL, DMODEL);
    gemm_tf32<<<gproj, 256>>>(x, Wv, bv, vp, MROWS, DMODEL, DMODEL);

    dim3 gattn(BATCH * NHEAD, SEQ / QT);     // (64, 16)
    attn_tf32<<<gattn, 256, attn_smem>>>(qp, kp, vp, cp);

    gemm_tf32<<<gproj, 256>>>(cp, Wo, bo, out, MROWS, DMODEL, DMODEL);
}

// round 5
// speedup vs baseline: 4.9662x; 1.0629x over previous
#include <cuda_runtime.h>
#include <math.h>
#include <stdint.h>

#define BATCH 4
#define SEQ   2048
#define DMODEL 2048
#define NHEAD 16
#define HDIM  128
#define MROWS (BATCH * SEQ)   // 8192

// Scratch (allocation-free rule: __device__ globals)
__device__ float g_q[(size_t)MROWS * DMODEL];
__device__ float g_k[(size_t)MROWS * DMODEL];
__device__ float g_v[(size_t)MROWS * DMODEL];
__device__ float g_ctx[(size_t)MROWS * DMODEL];

// ---------------------------------------------------------------------------
// helpers
// ---------------------------------------------------------------------------
__device__ __forceinline__ uint32_t f2tf(float x) {
    uint32_t r;
    asm("cvt.rna.tf32.f32 %0, %1;" : "=r"(r) : "f"(x));
    return r;
}

// D += A(16x8 row) * B(8x8 col),  tf32 inputs, fp32 accum
__device__ __forceinline__ void mma8(float* d, const uint32_t* a, const uint32_t* b) {
    asm volatile(
        "mma.sync.aligned.m16n8k8.row.col.f32.tf32.tf32.f32 "
        "{%0,%1,%2,%3}, {%4,%5,%6,%7}, {%8,%9}, {%0,%1,%2,%3};\n"
        : "+f"(d[0]), "+f"(d[1]), "+f"(d[2]), "+f"(d[3])
        : "r"(a[0]), "r"(a[1]), "r"(a[2]), "r"(a[3]),
          "r"(b[0]), "r"(b[1]));
}

__device__ __forceinline__ void cpa16(uint32_t sa, const void* g) {
    asm volatile("cp.async.cg.shared.global [%0], [%1], 16;\n" :: "r"(sa), "l"(g));
}
__device__ __forceinline__ void cpa_commit() {
    asm volatile("cp.async.commit_group;\n");
}
template <int N>
__device__ __forceinline__ void cpa_wait() {
    asm volatile("cp.async.wait_group %0;\n" :: "n"(N));
}

// ---------------------------------------------------------------------------
// TF32 GEMM:  C[M,N] = A[M,K] @ W[N,K]^T + bias[N]
// Block tile 128x128, BK=32, 256 threads, warp grid 2(m) x 4(n),
// warp tile 64x32. cp.async double-buffered smem staging (raw f32),
// tf32 conversion at fragment-load time (rna preserved).
// ---------------------------------------------------------------------------
#define ASTR 36   // stride == 4 (mod 32): fragment reads are a bank permutation
#define GTILE (128 * ASTR)

__global__ __launch_bounds__(256, 2) void gemm_tf32(
    const float* __restrict__ A, const float* __restrict__ W,
    const float* __restrict__ bias, float* __restrict__ C,
    int M, int N, int K)
{
    extern __shared__ float gsm[];
    float* As = gsm;              // [2][GTILE]
    float* Ws = gsm + 2 * GTILE;  // [2][GTILE]

    const int tid = threadIdx.x;
    const int l   = tid & 31;
    const int w   = tid >> 5;
    const int wm  = w >> 2;        // 0..1
    const int wn  = w & 3;         // 0..3
    const int lg  = l >> 2;        // 0..7
    const int lt  = l & 3;         // 0..3

    const int lr  = tid >> 3;      // 0..31? no: 0..31 -> rows handled per chunk
    const int lc4 = (tid & 7) * 4; // 0..28

    const float* Abase = A + (size_t)(blockIdx.y * 128) * K;
    const float* Wbase = W + (size_t)(blockIdx.x * 128) * K;

    const int NT = K / 32;

    // cp.async issue of one 128x32 tile pair into buffer `buf`
    auto issue = [&](int kt, int buf) {
        int k0 = kt * 32;
#pragma unroll
        for (int i = 0; i < 4; i++) {
            int r = lr + i * 32;   // tid>>3 in 0..31, +32*i -> 0..127
            uint32_t sa = (uint32_t)__cvta_generic_to_shared(
                &As[buf * GTILE + r * ASTR + lc4]);
            cpa16(sa, Abase + (size_t)r * K + k0 + lc4);
            uint32_t sw = (uint32_t)__cvta_generic_to_shared(
                &Ws[buf * GTILE + r * ASTR + lc4]);
            cpa16(sw, Wbase + (size_t)r * K + k0 + lc4);
        }
        cpa_commit();
    };

    float acc[4][4][4];
#pragma unroll
    for (int mi = 0; mi < 4; mi++)
#pragma unroll
        for (int nj = 0; nj < 4; nj++)
#pragma unroll
            for (int r = 0; r < 4; r++) acc[mi][nj][r] = 0.0f;

    issue(0, 0);

    for (int kt = 0; kt < NT; kt++) {
        int buf = kt & 1;
        if (kt + 1 < NT) {
            issue(kt + 1, buf ^ 1);
            cpa_wait<1>();           // tile kt has landed
        } else {
            cpa_wait<0>();
        }
        __syncthreads();

        const float* Ab = &As[buf * GTILE];
        const float* Wb = &Ws[buf * GTILE];
#pragma unroll
        for (int ks = 0; ks < 4; ks++) {
            int kk = ks * 8 + lt;
            uint32_t af[4][4], bf[4][2];
#pragma unroll
            for (int mi = 0; mi < 4; mi++) {
                int r0 = wm * 64 + mi * 16 + lg;
                af[mi][0] = f2tf(Ab[r0 * ASTR + kk]);
                af[mi][1] = f2tf(Ab[(r0 + 8) * ASTR + kk]);
                af[mi][2] = f2tf(Ab[r0 * ASTR + kk + 4]);
                af[mi][3] = f2tf(Ab[(r0 + 8) * ASTR + kk + 4]);
            }
#pragma unroll
            for (int nj = 0; nj < 4; nj++) {
                int c0 = wn * 32 + nj * 8 + lg;
                bf[nj][0] = f2tf(Wb[c0 * ASTR + kk]);
                bf[nj][1] = f2tf(Wb[c0 * ASTR + kk + 4]);
            }
#pragma unroll
            for (int mi = 0; mi < 4; mi++)
#pragma unroll
                for (int nj = 0; nj < 4; nj++)
                    mma8(acc[mi][nj], af[mi], bf[nj]);
        }
        __syncthreads();
    }

    // Epilogue
#pragma unroll
    for (int mi = 0; mi < 4; mi++) {
        int r = blockIdx.y * 128 + wm * 64 + mi * 16 + lg;
#pragma unroll
        for (int nj = 0; nj < 4; nj++) {
            int c = blockIdx.x * 128 + wn * 32 + nj * 8 + lt * 2;
            float b0 = bias[c], b1 = bias[c + 1];
            float2 o0 = make_float2(acc[mi][nj][0] + b0, acc[mi][nj][1] + b1);
            float2 o1 = make_float2(acc[mi][nj][2] + b0, acc[mi][nj][3] + b1);
            *(float2*)(C + (size_t)r * N + c)       = o0;
            *(float2*)(C + (size_t)(r + 8) * N + c) = o1;
        }
    }
}

// ---------------------------------------------------------------------------
// TF32 flash attention, register-prefetch pipeline.
// Q-tile 128 x K-tile 64, 256 threads, 8 warps; warp w owns S/O rows
// [w*16, w*16+16). Separate K and V smem buffers; per iteration:
//   barA; store K (cvt), issue LDG V; barB; S-mma; softmax->Ps (warp-private);
//   store V (cvt), issue LDG next-K; barC; PV-mma.
// 2 gmem latencies fully hidden, 3 bars/iter (barA is barC of prev+loop top).
// Strides: QSTR/KSTR/PSTR == 4 (mod 32); VSTR == 8 (mod 32) -> all fragment
// reads conflict-free.
// ---------------------------------------------------------------------------
#define QT 128
#define KT 64
#define QSTR 132
#define KSTR 132
#define VSTR 136
#define PSTR 68

__global__ __launch_bounds__(256) void attn_tf32(
    const float* __restrict__ Q, const float* __restrict__ K,
    const float* __restrict__ V, float* __restrict__ O)
{
    extern __shared__ uint32_t sm[];
    uint32_t* Qs = sm;                       // 128 x QSTR
    uint32_t* Ks = Qs + QT * QSTR;           // 64 x KSTR
    uint32_t* Vs = Ks + KT * KSTR;           // 64 x VSTR
    uint32_t* Ps = Vs + KT * VSTR;           // 128 x PSTR

    const int tid = threadIdx.x;
    const int l   = tid & 31;
    const int w   = tid >> 5;
    const int lg  = l >> 2;
    const int lt  = l & 3;
    const int b   = blockIdx.x >> 4;
    const int h   = blockIdx.x & 15;
    const int q0  = blockIdx.y * QT;
    const int r0  = w * 16 + lg;

    const size_t base = (size_t)b * SEQ * DMODEL + (size_t)h * HDIM;
    const float scale = 0.08838834764831845f; // 1/sqrt(128), folded into Q

    // Load + scale + cvt Q tile (128 x 128)
#pragma unroll
    for (int i = 0; i < 16; i++) {
        int idx = tid + i * 256;
        int r = idx >> 5, c4 = (idx & 31) * 4;
        float4 qv = *(const float4*)(Q + base + (size_t)(q0 + r) * DMODEL + c4);
        uint4 u; u.x = f2tf(qv.x * scale); u.y = f2tf(qv.y * scale);
                 u.z = f2tf(qv.z * scale); u.w = f2tf(qv.w * scale);
        *(uint4*)&Qs[r * QSTR + c4] = u;
    }

    // Prefetch first K tile into registers (8 float4 per thread)
    float4 pf[8];
#pragma unroll
    for (int i = 0; i < 8; i++) {
        int idx = tid + i * 256;
        int r = idx >> 5, c4 = (idx & 31) * 4;
        pf[i] = *(const float4*)(K + base + (size_t)r * DMODEL + c4);
    }

    float o[16][4];
#pragma unroll
    for (int j = 0; j < 16; j++)
#pragma unroll
        for (int r = 0; r < 4; r++) o[j][r] = 0.0f;
    float m_lo = -INFINITY, m_hi = -INFINITY, l_lo = 0.0f, l_hi = 0.0f;

    for (int k0 = 0; k0 < SEQ; k0 += KT) {
        __syncthreads();   // barA: prev PV done (Vs, Ps); prev S done (Ks)

        // store K tile (cvt) and kick off V tile loads into the same regs
#pragma unroll
        for (int i = 0; i < 8; i++) {
            int idx = tid + i * 256;
            int r = idx >> 5, c4 = (idx & 31) * 4;
            uint4 u; u.x = f2tf(pf[i].x); u.y = f2tf(pf[i].y);
                     u.z = f2tf(pf[i].z); u.w = f2tf(pf[i].w);
            *(uint4*)&Ks[r * KSTR + c4] = u;
            pf[i] = *(const float4*)(V + base + (size_t)(k0 + r) * DMODEL + c4);
        }
        __syncthreads();   // barB: Ks (and, iter 0, Qs) visible

        // S = Q_tile @ K_tile^T  (this warp's 16 rows x 64 keys)
        float s[8][4];
#pragma unroll
        for (int j = 0; j < 8; j++)
#pragma unroll
            for (int r = 0; r < 4; r++) s[j][r] = 0.0f;
#pragma unroll
        for (int ks = 0; ks < 16; ks++) {
            int kk = ks * 8 + lt;
            uint32_t af[4];
            af[0] = Qs[r0 * QSTR + kk];
            af[1] = Qs[(r0 + 8) * QSTR + kk];
            af[2] = Qs[r0 * QSTR + kk + 4];
            af[3] = Qs[(r0 + 8) * QSTR + kk + 4];
#pragma unroll
            for (int j = 0; j < 8; j++) {
                int c0 = j * 8 + lg;
                uint32_t bf[2];
                bf[0] = Ks[c0 * KSTR + kk];
                bf[1] = Ks[c0 * KSTR + kk + 4];
                mma8(s[j], af, bf);
            }
        }

        // Online softmax (rows r0 and r0+8; 4 lanes per row)
        float mlo = -INFINITY, mhi = -INFINITY;
#pragma unroll
        for (int j = 0; j < 8; j++) {
            mlo = fmaxf(mlo, fmaxf(s[j][0], s[j][1]));
            mhi = fmaxf(mhi, fmaxf(s[j][2], s[j][3]));
        }
        mlo = fmaxf(mlo, __shfl_xor_sync(0xffffffffu, mlo, 1));
        mlo = fmaxf(mlo, __shfl_xor_sync(0xffffffffu, mlo, 2));
        mhi = fmaxf(mhi, __shfl_xor_sync(0xffffffffu, mhi, 1));
        mhi = fmaxf(mhi, __shfl_xor_sync(0xffffffffu, mhi, 2));
        float mnl = fmaxf(m_lo, mlo), mnh = fmaxf(m_hi, mhi);
        float al = __expf(m_lo - mnl), ah = __expf(m_hi - mnh);

        float pl = 0.0f, ph = 0.0f;
#pragma unroll
        for (int j = 0; j < 8; j++) {
            float p0 = __expf(s[j][0] - mnl);
            float p1 = __expf(s[j][1] - mnl);
            float p2 = __expf(s[j][2] - mnh);
            float p3 = __expf(s[j][3] - mnh);
            pl += p0 + p1; ph += p2 + p3;
            int c = j * 8 + lt * 2;
            Ps[r0 * PSTR + c]           = f2tf(p0);
            Ps[r0 * PSTR + c + 1]       = f2tf(p1);
            Ps[(r0 + 8) * PSTR + c]     = f2tf(p2);
            Ps[(r0 + 8) * PSTR + c + 1] = f2tf(p3);
        }
        pl += __shfl_xor_sync(0xffffffffu, pl, 1);
        pl += __shfl_xor_sync(0xffffffffu, pl, 2);
        ph += __shfl_xor_sync(0xffffffffu, ph, 1);
        ph += __shfl_xor_sync(0xffffffffu, ph, 2);
        l_lo = l_lo * al + pl;
        l_hi = l_hi * ah + ph;
        m_lo = mnl; m_hi = mnh;
#pragma unroll
        for (int j = 0; j < 16; j++) {
            o[j][0] *= al; o[j][1] *= al;
            o[j][2] *= ah; o[j][3] *= ah;
        }

        // store V tile (cvt) and kick off next K tile loads
        const int kn = (k0 + KT < SEQ) ? (k0 + KT) : 0;   // harmless reload on last iter
#pragma unroll
        for (int i = 0; i < 8; i++) {
            int idx = tid + i * 256;
            int r = idx >> 5, c4 = (idx & 31) * 4;
            uint4 u; u.x = f2tf(pf[i].x); u.y = f2tf(pf[i].y);
                     u.z = f2tf(pf[i].z); u.w = f2tf(pf[i].w);
            *(uint4*)&Vs[r * VSTR + c4] = u;
            pf[i] = *(const float4*)(K + base + (size_t)(kn + r) * DMODEL + c4);
        }
        __syncthreads();   // barC: Vs + Ps visible

        // O += P @ V  (16 rows x 128 dims, k over 64 keys)
#pragma unroll
        for (int ks = 0; ks < 8; ks++) {
            int kk = ks * 8 + lt;
            uint32_t af[4];
            af[0] = Ps[r0 * PSTR + kk];
            af[1] = Ps[(r0 + 8) * PSTR + kk];
            af[2] = Ps[r0 * PSTR + kk + 4];
            af[3] = Ps[(r0 + 8) * PSTR + kk + 4];
#pragma unroll
            for (int j = 0; j < 16; j++) {
                int c0 = j * 8 + lg;
                uint32_t bf[2];
                bf[0] = Vs[kk * VSTR + c0];
                bf[1] = Vs[(kk + 4) * VSTR + c0];
                mma8(o[j], af, bf);
            }
        }
    }

    // Normalize and store
    float il = 1.0f / l_lo, ih = 1.0f / l_hi;
    float* orow0 = O + base + (size_t)(q0 + r0) * DMODEL;
    float* orow1 = O + base + (size_t)(q0 + r0 + 8) * DMODEL;
#pragma unroll
    for (int j = 0; j < 16; j++) {
        int c = j * 8 + lt * 2;
        *(float2*)(orow0 + c) = make_float2(o[j][0] * il, o[j][1] * il);
        *(float2*)(orow1 + c) = make_float2(o[j][2] * ih, o[j][3] * ih);
    }
}

// ---------------------------------------------------------------------------
extern "C" void kernel_launch(void* const* d_in, const int* in_sizes, int n_in,
                              void* d_out, int out_size)
{
    const float* x  = (const float*)d_in[0];
    const float* Wq = (const float*)d_in[1];
    const float* bq = (const float*)d_in[2];
    const float* Wk = (const float*)d_in[3];
    const float* bk = (const float*)d_in[4];
    const float* Wv = (const float*)d_in[5];
    const float* bv = (const float*)d_in[6];
    const float* Wo = (const float*)d_in[7];
    const float* bo = (const float*)d_in[8];
    float* out = (float*)d_out;

    float *qp, *kp, *vp, *cp;
    cudaGetSymbolAddress((void**)&qp, g_q);
    cudaGetSymbolAddress((void**)&kp, g_k);
    cudaGetSymbolAddress((void**)&vp, g_v);
    cudaGetSymbolAddress((void**)&cp, g_ctx);

    const int gemm_smem = 4 * GTILE * 4;   // 73728 B (A+W, double-buffered)
    const int attn_smem = (QT * QSTR + KT * KSTR + KT * VSTR + QT * PSTR) * 4; // 171008 B
    cudaFuncSetAttribute(gemm_tf32, cudaFuncAttributeMaxDynamicSharedMemorySize,
                         gemm_smem);
    cudaFuncSetAttribute(attn_tf32, cudaFuncAttributeMaxDynamicSharedMemorySize,
                         attn_smem);

    dim3 gproj(DMODEL / 128, MROWS / 128);   // (16, 64)
    gemm_tf32<<<gproj, 256, gemm_smem>>>(x, Wq, bq, qp, MROWS, DMODEL, DMODEL);
    gemm_tf32<<<gproj, 256, gemm_smem>>>(x, Wk, bk, kp, MROWS, DMODEL, DMODEL);
    gemm_tf32<<<gproj, 256, gemm_smem>>>(x, Wv, bv, vp, MROWS, DMODEL, DMODEL);

    dim3 gattn(BATCH * NHEAD, SEQ / QT);     // (64, 16)
    attn_tf32<<<gattn, 256, attn_smem>>>(qp, kp, vp, cp);

    gemm_tf32<<<gproj, 256, gemm_smem>>>(cp, Wo, bo, out, MROWS, DMODEL, DMODEL);
}

// round 8
// speedup vs baseline: 5.5539x; 1.1183x over previous
#include <cuda_runtime.h>
#include <cuda_fp16.h>
#include <math.h>
#include <stdint.h>

#define BATCH 4
#define SEQ   2048
#define DMODEL 2048
#define NHEAD 16
#define HDIM  128
#define MROWS (BATCH * SEQ)   // 8192

// Scratch (allocation-free rule: __device__ globals)
__device__ float g_q[(size_t)MROWS * DMODEL];
__device__ float g_k[(size_t)MROWS * DMODEL];
__device__ float g_v[(size_t)MROWS * DMODEL];
__device__ float g_ctx[(size_t)MROWS * DMODEL];

// ---------------------------------------------------------------------------
// helpers
// ---------------------------------------------------------------------------
__device__ __forceinline__ uint32_t h2pack(float lo, float hi) {
    __half2 h = __floats2half2_rn(lo, hi);   // x=lo, y=hi
    return *reinterpret_cast<uint32_t*>(&h);
}

// D += A(16x16 row) * B(16x8 col),  fp16 inputs, fp32 accum
__device__ __forceinline__ void mma16(float* d, const uint32_t* a, const uint32_t* b) {
    asm volatile(
        "mma.sync.aligned.m16n8k16.row.col.f32.f16.f16.f32 "
        "{%0,%1,%2,%3}, {%4,%5,%6,%7}, {%8,%9}, {%0,%1,%2,%3};\n"
        : "+f"(d[0]), "+f"(d[1]), "+f"(d[2]), "+f"(d[3])
        : "r"(a[0]), "r"(a[1]), "r"(a[2]), "r"(a[3]),
          "r"(b[0]), "r"(b[1]));
}

// ---------------------------------------------------------------------------
// FP16 GEMM:  C[M,N] = A[M,K] @ W[N,K]^T + bias[N]
// Block tile 128x128, chunk K=32 (16 half2 words/row), 256 threads,
// warp grid 2(m) x 4(n), warp tile 64x32. Register-prefetch staging:
// load f32 chunk i+1 while mma runs on chunk i. Stride 20 words (== 20 mod 32,
// 20*lg+lt a bank permutation) -> conflict-free fragment reads.
// ---------------------------------------------------------------------------
#define GSTR 20
#define GT (128 * GSTR)

__global__ __launch_bounds__(256, 2) void gemm_fp16(
    const float* __restrict__ A, const float* __restrict__ W,
    const float* __restrict__ bias, float* __restrict__ C,
    int M, int N, int K)
{
    __shared__ uint32_t As[GT];
    __shared__ uint32_t Ws[GT];

    const int tid = threadIdx.x;
    const int l   = tid & 31;
    const int w   = tid >> 5;
    const int wm  = w >> 2;        // 0..1
    const int wn  = w & 3;         // 0..3
    const int lg  = l >> 2;        // 0..7
    const int lt  = l & 3;         // 0..3

    const int ra  = tid >> 1;          // 0..127 staging row
    const int seg = (tid & 1) * 16;    // k-float offset 0 or 16

    const float* Ap = A + (size_t)(blockIdx.y * 128 + ra) * K + seg;
    const float* Wp = W + (size_t)(blockIdx.x * 128 + ra) * K + seg;

    float acc[4][4][4];
#pragma unroll
    for (int mi = 0; mi < 4; mi++)
#pragma unroll
        for (int nj = 0; nj < 4; nj++)
#pragma unroll
            for (int r = 0; r < 4; r++) acc[mi][nj][r] = 0.0f;

    // prefetch chunk 0
    float4 pa[4], pb[4];
#pragma unroll
    for (int i = 0; i < 4; i++) {
        pa[i] = *(const float4*)(Ap + i * 4);
        pb[i] = *(const float4*)(Wp + i * 4);
    }

    const int NCH = K / 32;
    for (int c = 0; c < NCH; c++) {
        __syncthreads();   // prev mma reads done
        // store chunk c (cvt to half2), prefetch chunk c+1
#pragma unroll
        for (int i = 0; i < 4; i++) {
            uint2 ua = make_uint2(h2pack(pa[i].x, pa[i].y), h2pack(pa[i].z, pa[i].w));
            uint2 uw = make_uint2(h2pack(pb[i].x, pb[i].y), h2pack(pb[i].z, pb[i].w));
            *(uint2*)&As[ra * GSTR + (seg >> 1) + i * 2] = ua;
            *(uint2*)&Ws[ra * GSTR + (seg >> 1) + i * 2] = uw;
        }
        if (c + 1 < NCH) {
            const float* Ap2 = Ap + (c + 1) * 32;
            const float* Wp2 = Wp + (c + 1) * 32;
#pragma unroll
            for (int i = 0; i < 4; i++) {
                pa[i] = *(const float4*)(Ap2 + i * 4);
                pb[i] = *(const float4*)(Wp2 + i * 4);
            }
        }
        __syncthreads();

#pragma unroll
        for (int ks = 0; ks < 2; ks++) {
            int kk = ks * 8 + lt;
            uint32_t af[4][4], bf[4][2];
#pragma unroll
            for (int mi = 0; mi < 4; mi++) {
                int r0 = wm * 64 + mi * 16 + lg;
                af[mi][0] = As[r0 * GSTR + kk];
                af[mi][1] = As[(r0 + 8) * GSTR + kk];
                af[mi][2] = As[r0 * GSTR + kk + 4];
                af[mi][3] = As[(r0 + 8) * GSTR + kk + 4];
            }
#pragma unroll
            for (int nj = 0; nj < 4; nj++) {
                int c0 = wn * 32 + nj * 8 + lg;
                bf[nj][0] = Ws[c0 * GSTR + kk];
                bf[nj][1] = Ws[c0 * GSTR + kk + 4];
            }
#pragma unroll
            for (int mi = 0; mi < 4; mi++)
#pragma unroll
                for (int nj = 0; nj < 4; nj++)
                    mma16(acc[mi][nj], af[mi], bf[nj]);
        }
    }

    // Epilogue: d0,d1 -> (r, 2lt),(r, 2lt+1); d2,d3 -> row+8
#pragma unroll
    for (int mi = 0; mi < 4; mi++) {
        int r = blockIdx.y * 128 + wm * 64 + mi * 16 + lg;
#pragma unroll
        for (int nj = 0; nj < 4; nj++) {
            int cc = blockIdx.x * 128 + wn * 32 + nj * 8 + lt * 2;
            float b0 = bias[cc], b1 = bias[cc + 1];
            float2 o0 = make_float2(acc[mi][nj][0] + b0, acc[mi][nj][1] + b1);
            float2 o1 = make_float2(acc[mi][nj][2] + b0, acc[mi][nj][3] + b1);
            *(float2*)(C + (size_t)r * N + cc)       = o0;
            *(float2*)(C + (size_t)(r + 8) * N + cc) = o1;
        }
    }
}

// ---------------------------------------------------------------------------
// FP16 flash attention, register-prefetch pipeline.
// Q-tile 128 x K-tile 64, 256 threads, 8 warps; warp w owns S/O rows
// [w*16, w*16+16). half2-packed k-pairs everywhere.
//   Qs/Ks: [row][pairk]  stride 68 (==4 mod 32)
//   Ps:    [row][pairk]  stride 36 (==4 mod 32)
//   Vs:    [pairk][n]    stride 136 (==8 mod 32), word = (V[2k][n],V[2k+1][n])
// Per iteration: barA; store K, LDG V; barB; S-mma(8 ks); softmax -> Ps;
// store V (pair-transposed), LDG next K; barC; PV-mma(4 ks).
// ---------------------------------------------------------------------------
#define QT 128
#define KT 64
#define QSTR 68
#define KSTR 68
#define VSTR 136
#define PSTR 36

__global__ __launch_bounds__(256) void attn_fp16(
    const float* __restrict__ Q, const float* __restrict__ K,
    const float* __restrict__ V, float* __restrict__ O)
{
    extern __shared__ uint32_t sm[];
    uint32_t* Qs = sm;                       // 128 x QSTR
    uint32_t* Ks = Qs + QT * QSTR;           // 64 x KSTR
    uint32_t* Vs = Ks + KT * KSTR;           // 32 x VSTR
    uint32_t* Ps = Vs + 32 * VSTR;           // 128 x PSTR

    const int tid = threadIdx.x;
    const int l   = tid & 31;
    const int w   = tid >> 5;
    const int lg  = l >> 2;
    const int lt  = l & 3;
    const int b   = blockIdx.x >> 4;
    const int h   = blockIdx.x & 15;
    const int q0  = blockIdx.y * QT;
    const int r0  = w * 16 + lg;

    const int pr  = tid >> 3;        // 0..31: V pair row
    const int nc  = tid & 7;         // 0..7 : V n-subcolumn

    const size_t base = (size_t)b * SEQ * DMODEL + (size_t)h * HDIM;
    const float scale = 0.08838834764831845f;   // 1/sqrt(128), folded into Q

    // Load + scale + pack Q tile (128 x 128)
#pragma unroll
    for (int i = 0; i < 16; i++) {
        int idx = tid + i * 256;
        int r = idx >> 5, c4 = (idx & 31) * 4;
        float4 qv = *(const float4*)(Q + base + (size_t)(q0 + r) * DMODEL + c4);
        uint2 u = make_uint2(h2pack(qv.x * scale, qv.y * scale),
                             h2pack(qv.z * scale, qv.w * scale));
        *(uint2*)&Qs[r * QSTR + (c4 >> 1)] = u;
    }

    // Prefetch first K tile (8 float4 per thread)
    float4 pf[8];
#pragma unroll
    for (int i = 0; i < 8; i++) {
        int idx = tid + i * 256;
        int r = idx >> 5, c4 = (idx & 31) * 4;
        pf[i] = *(const float4*)(K + base + (size_t)r * DMODEL + c4);
    }

    float o[16][4];
#pragma unroll
    for (int j = 0; j < 16; j++)
#pragma unroll
        for (int r = 0; r < 4; r++) o[j][r] = 0.0f;
    float m_lo = -INFINITY, m_hi = -INFINITY, l_lo = 0.0f, l_hi = 0.0f;

    for (int k0 = 0; k0 < SEQ; k0 += KT) {
        __syncthreads();   // barA: prev PV (Vs,Ps) and prev S (Ks) done

        // store K tile (pack), kick off V loads (pair-transposed pattern)
#pragma unroll
        for (int i = 0; i < 8; i++) {
            int idx = tid + i * 256;
            int r = idx >> 5, c4 = (idx & 31) * 4;
            uint2 u = make_uint2(h2pack(pf[i].x, pf[i].y), h2pack(pf[i].z, pf[i].w));
            *(uint2*)&Ks[r * KSTR + (c4 >> 1)] = u;
        }
#pragma unroll
        for (int i = 0; i < 8; i++) {
            int n0 = i * 16 + nc * 2;
            const float* v0 = V + base + (size_t)(k0 + 2 * pr) * DMODEL + n0;
            float2 a = *(const float2*)v0;
            float2 c = *(const float2*)(v0 + DMODEL);
            pf[i] = make_float4(a.x, a.y, c.x, c.y);
        }
        __syncthreads();   // barB: Ks (iter 0: +Qs) visible

        // S = Q @ K^T : 8 ksteps of k16
        float s[8][4];
#pragma unroll
        for (int j = 0; j < 8; j++)
#pragma unroll
            for (int r = 0; r < 4; r++) s[j][r] = 0.0f;
#pragma unroll
        for (int ks = 0; ks < 8; ks++) {
            int kk = ks * 8 + lt;
            uint32_t af[4];
            af[0] = Qs[r0 * QSTR + kk];
            af[1] = Qs[(r0 + 8) * QSTR + kk];
            af[2] = Qs[r0 * QSTR + kk + 4];
            af[3] = Qs[(r0 + 8) * QSTR + kk + 4];
#pragma unroll
            for (int j = 0; j < 8; j++) {
                int c0 = j * 8 + lg;
                uint32_t bf[2];
                bf[0] = Ks[c0 * KSTR + kk];
                bf[1] = Ks[c0 * KSTR + kk + 4];
                mma16(s[j], af, bf);
            }
        }

        // Online softmax (rows r0, r0+8; 4 lanes per row)
        float mlo = -INFINITY, mhi = -INFINITY;
#pragma unroll
        for (int j = 0; j < 8; j++) {
            mlo = fmaxf(mlo, fmaxf(s[j][0], s[j][1]));
            mhi = fmaxf(mhi, fmaxf(s[j][2], s[j][3]));
        }
        mlo = fmaxf(mlo, __shfl_xor_sync(0xffffffffu, mlo, 1));
        mlo = fmaxf(mlo, __shfl_xor_sync(0xffffffffu, mlo, 2));
        mhi = fmaxf(mhi, __shfl_xor_sync(0xffffffffu, mhi, 1));
        mhi = fmaxf(mhi, __shfl_xor_sync(0xffffffffu, mhi, 2));
        float mnl = fmaxf(m_lo, mlo), mnh = fmaxf(m_hi, mhi);
        float al = __expf(m_lo - mnl), ah = __expf(m_hi - mnh);

        float pl = 0.0f, ph = 0.0f;
#pragma unroll
        for (int j = 0; j < 8; j++) {
            float p0 = __expf(s[j][0] - mnl);
            float p1 = __expf(s[j][1] - mnl);
            float p2 = __expf(s[j][2] - mnh);
            float p3 = __expf(s[j][3] - mnh);
            pl += p0 + p1; ph += p2 + p3;
            int pw = j * 4 + lt;                 // pair index = (j*8 + 2lt)/2
            Ps[r0 * PSTR + pw]       = h2pack(p0, p1);
            Ps[(r0 + 8) * PSTR + pw] = h2pack(p2, p3);
        }
        pl += __shfl_xor_sync(0xffffffffu, pl, 1);
        pl += __shfl_xor_sync(0xffffffffu, pl, 2);
        ph += __shfl_xor_sync(0xffffffffu, ph, 1);
        ph += __shfl_xor_sync(0xffffffffu, ph, 2);
        l_lo = l_lo * al + pl;
        l_hi = l_hi * ah + ph;
        m_lo = mnl; m_hi = mnh;
#pragma unroll
        for (int j = 0; j < 16; j++) {
            o[j][0] *= al; o[j][1] *= al;
            o[j][2] *= ah; o[j][3] *= ah;
        }

        // store V (pair-transposed pack), kick off next K loads
        const int kn = (k0 + KT < SEQ) ? (k0 + KT) : 0;
#pragma unroll
        for (int i = 0; i < 8; i++) {
            int n0 = i * 16 + nc * 2;
            uint2 u = make_uint2(h2pack(pf[i].x, pf[i].z),   // (V[2k][n], V[2k+1][n])
                                 h2pack(pf[i].y, pf[i].w));  // (V[2k][n+1], V[2k+1][n+1])
            *(uint2*)&Vs[pr * VSTR + n0] = u;
        }
#pragma unroll
        for (int i = 0; i < 8; i++) {
            int idx = tid + i * 256;
            int r = idx >> 5, c4 = (idx & 31) * 4;
            pf[i] = *(const float4*)(K + base + (size_t)(kn + r) * DMODEL + c4);
        }
        __syncthreads();   // barC: Vs + Ps visible

        // O += P @ V : 4 ksteps of k16, 16 n-tiles
#pragma unroll
        for (int ks = 0; ks < 4; ks++) {
            int kk = ks * 8 + lt;
            uint32_t af[4];
            af[0] = Ps[r0 * PSTR + kk];
            af[1] = Ps[(r0 + 8) * PSTR + kk];
            af[2] = Ps[r0 * PSTR + kk + 4];
            af[3] = Ps[(r0 + 8) * PSTR + kk + 4];
#pragma unroll
            for (int j = 0; j < 16; j++) {
                int c0 = j * 8 + lg;
                uint32_t bf[2];
                bf[0] = Vs[kk * VSTR + c0];
                bf[1] = Vs[(kk + 4) * VSTR + c0];
                mma16(o[j], af, bf);
            }
        }
    }

    // Normalize and store
    float il = 1.0f / l_lo, ih = 1.0f / l_hi;
    float* orow0 = O + base + (size_t)(q0 + r0) * DMODEL;
    float* orow1 = O + base + (size_t)(q0 + r0 + 8) * DMODEL;
#pragma unroll
    for (int j = 0; j < 16; j++) {
        int c = j * 8 + lt * 2;
        *(float2*)(orow0 + c) = make_float2(o[j][0] * il, o[j][1] * il);
        *(float2*)(orow1 + c) = make_float2(o[j][2] * ih, o[j][3] * ih);
    }
}

// ---------------------------------------------------------------------------
extern "C" void kernel_launch(void* const* d_in, const int* in_sizes, int n_in,
                              void* d_out, int out_size)
{
    const float* x  = (const float*)d_in[0];
    const float* Wq = (const float*)d_in[1];
    const float* bq = (const float*)d_in[2];
    const float* Wk = (const float*)d_in[3];
    const float* bk = (const float*)d_in[4];
    const float* Wv = (const float*)d_in[5];
    const float* bv = (const float*)d_in[6];
    const float* Wo = (const float*)d_in[7];
    const float* bo = (const float*)d_in[8];
    float* out = (float*)d_out;

    float *qp, *kp, *vp, *cp;
    cudaGetSymbolAddress((void**)&qp, g_q);
    cudaGetSymbolAddress((void**)&kp, g_k);
    cudaGetSymbolAddress((void**)&vp, g_v);
    cudaGetSymbolAddress((void**)&cp, g_ctx);

    const int attn_smem = (QT * QSTR + KT * KSTR + 32 * VSTR + QT * PSTR) * 4; // 88064 B
    cudaFuncSetAttribute(attn_fp16, cudaFuncAttributeMaxDynamicSharedMemorySize,
                         attn_smem);

    dim3 gproj(DMODEL / 128, MROWS / 128);   // (16, 64)
    gemm_fp16<<<gproj, 256>>>(x, Wq, bq, qp, MROWS, DMODEL, DMODEL);
    gemm_fp16<<<gproj, 256>>>(x, Wk, bk, kp, MROWS, DMODEL, DMODEL);
    gemm_fp16<<<gproj, 256>>>(x, Wv, bv, vp, MROWS, DMODEL, DMODEL);

    dim3 gattn(BATCH * NHEAD, SEQ / QT);     // (64, 16)
    attn_fp16<<<gattn, 256, attn_smem>>>(qp, kp, vp, cp);

    gemm_fp16<<<gproj, 256>>>(cp, Wo, bo, out, MROWS, DMODEL, DMODEL);
}

// round 9
// speedup vs baseline: 7.2186x; 1.2997x over previous
#include <cuda_runtime.h>
#include <cuda_fp16.h>
#include <math.h>
#include <stdint.h>

#define BATCH 4
#define SEQ   2048
#define DMODEL 2048
#define NHEAD 16
#define HDIM  128
#define MROWS (BATCH * SEQ)   // 8192

// Scratch (allocation-free rule: __device__ globals) — fp16 activations
__device__ __half g_q[(size_t)MROWS * DMODEL];
__device__ __half g_k[(size_t)MROWS * DMODEL];
__device__ __half g_v[(size_t)MROWS * DMODEL];
__device__ __half g_ctx[(size_t)MROWS * DMODEL];

// ---------------------------------------------------------------------------
// helpers
// ---------------------------------------------------------------------------
__device__ __forceinline__ uint32_t h2pack(float lo, float hi) {
    __half2 h = __floats2half2_rn(lo, hi);
    return *reinterpret_cast<uint32_t*>(&h);
}

// D += A(16x16 row) * B(16x8 col), fp16 in, fp32 accum
__device__ __forceinline__ void mma16(float* d, const uint32_t* a, const uint32_t* b) {
    asm volatile(
        "mma.sync.aligned.m16n8k16.row.col.f32.f16.f16.f32 "
        "{%0,%1,%2,%3}, {%4,%5,%6,%7}, {%8,%9}, {%0,%1,%2,%3};\n"
        : "+f"(d[0]), "+f"(d[1]), "+f"(d[2]), "+f"(d[3])
        : "r"(a[0]), "r"(a[1]), "r"(a[2]), "r"(a[3]),
          "r"(b[0]), "r"(b[1]));
}

__device__ __forceinline__ void ldsm4(uint32_t* r, uint32_t addr) {
    asm volatile("ldmatrix.sync.aligned.m8n8.x4.shared.b16 {%0,%1,%2,%3}, [%4];"
                 : "=r"(r[0]), "=r"(r[1]), "=r"(r[2]), "=r"(r[3]) : "r"(addr));
}
__device__ __forceinline__ void ldsm4t(uint32_t* r, uint32_t addr) {
    asm volatile("ldmatrix.sync.aligned.m8n8.x4.trans.shared.b16 {%0,%1,%2,%3}, [%4];"
                 : "=r"(r[0]), "=r"(r[1]), "=r"(r[2]), "=r"(r[3]) : "r"(addr));
}

__device__ __forceinline__ void cpa16(uint32_t sa, const void* g) {
    asm volatile("cp.async.cg.shared.global [%0], [%1], 16;\n" :: "r"(sa), "l"(g));
}
__device__ __forceinline__ void cpa_commit() {
    asm volatile("cp.async.commit_group;\n");
}
template <int N>
__device__ __forceinline__ void cpa_wait() {
    asm volatile("cp.async.wait_group %0;\n" :: "n"(N));
}
__device__ __forceinline__ uint32_t smem_u32(const void* p) {
    return (uint32_t)__cvta_generic_to_shared(p);
}

// ---------------------------------------------------------------------------
// GEMM common geometry: block 128x128, chunk K=32, 256 thr, warps 2(m)x4(n),
// warp tile 64x32. Smem stride GSTR=20 words (row base ≡ 20i mod 32 -> each
// 8-lane ldmatrix phase hits all 32 banks exactly once).
// ---------------------------------------------------------------------------
#define GSTR 20

// A=f32, C=half (scaled): projections (q gets scale=1/sqrt(dh), k/v scale=1)
__global__ __launch_bounds__(256, 2) void gemm_f2h(
    const float* __restrict__ A, const float* __restrict__ W,
    const float* __restrict__ bias, __half* __restrict__ C,
    float scale, int M, int N, int K)
{
    __shared__ uint32_t As[128 * GSTR];
    __shared__ uint32_t Ws[128 * GSTR];

    const int tid = threadIdx.x;
    const int l  = tid & 31, w = tid >> 5;
    const int wm = w >> 2, wn = w & 3, lg = l >> 2, lt = l & 3;
    const int ra = tid >> 1, seg = (tid & 1) * 16;

    const float* Ap = A + (size_t)(blockIdx.y * 128 + ra) * K + seg;
    const float* Wp = W + (size_t)(blockIdx.x * 128 + ra) * K + seg;

    const uint32_t ash = smem_u32(As), wsh = smem_u32(Ws);
    const uint32_t a_off = ((wm * 64 + (l & 7) + ((l >> 3) & 1) * 8) * GSTR
                           + (l >> 4) * 4) * 4;
    const uint32_t b_off = ((wn * 32 + (l >> 4) * 8 + (l & 7)) * GSTR
                           + ((l >> 3) & 1) * 4) * 4;

    float acc[4][4][4];
#pragma unroll
    for (int mi = 0; mi < 4; mi++)
#pragma unroll
        for (int nj = 0; nj < 4; nj++)
#pragma unroll
            for (int r = 0; r < 4; r++) acc[mi][nj][r] = 0.0f;

    float4 pa[4], pb[4];
#pragma unroll
    for (int i = 0; i < 4; i++) {
        pa[i] = *(const float4*)(Ap + i * 4);
        pb[i] = *(const float4*)(Wp + i * 4);
    }

    const int NCH = K / 32;
    for (int c = 0; c < NCH; c++) {
        __syncthreads();
#pragma unroll
        for (int i = 0; i < 4; i++) {
            uint2 ua = make_uint2(h2pack(pa[i].x, pa[i].y), h2pack(pa[i].z, pa[i].w));
            uint2 uw = make_uint2(h2pack(pb[i].x, pb[i].y), h2pack(pb[i].z, pb[i].w));
            *(uint2*)&As[ra * GSTR + (seg >> 1) + i * 2] = ua;
            *(uint2*)&Ws[ra * GSTR + (seg >> 1) + i * 2] = uw;
        }
        if (c + 1 < NCH) {
            const float* Ap2 = Ap + (c + 1) * 32;
            const float* Wp2 = Wp + (c + 1) * 32;
#pragma unroll
            for (int i = 0; i < 4; i++) {
                pa[i] = *(const float4*)(Ap2 + i * 4);
                pb[i] = *(const float4*)(Wp2 + i * 4);
            }
        }
        __syncthreads();

#pragma unroll
        for (int ks = 0; ks < 2; ks++) {
            uint32_t af[4][4], bf[2][4];
#pragma unroll
            for (int mi = 0; mi < 4; mi++)
                ldsm4(af[mi], ash + a_off + (mi * 16 * GSTR + ks * 8) * 4);
#pragma unroll
            for (int j2 = 0; j2 < 2; j2++)
                ldsm4(bf[j2], wsh + b_off + (j2 * 16 * GSTR + ks * 8) * 4);
#pragma unroll
            for (int mi = 0; mi < 4; mi++)
#pragma unroll
                for (int nj = 0; nj < 4; nj++)
                    mma16(acc[mi][nj], af[mi], &bf[nj >> 1][(nj & 1) * 2]);
        }
    }

#pragma unroll
    for (int mi = 0; mi < 4; mi++) {
        int r = blockIdx.y * 128 + wm * 64 + mi * 16 + lg;
#pragma unroll
        for (int nj = 0; nj < 4; nj++) {
            int cc = blockIdx.x * 128 + wn * 32 + nj * 8 + lt * 2;
            float b0 = bias[cc], b1 = bias[cc + 1];
            *(__half2*)(C + (size_t)r * N + cc) =
                __floats2half2_rn((acc[mi][nj][0] + b0) * scale,
                                  (acc[mi][nj][1] + b1) * scale);
            *(__half2*)(C + (size_t)(r + 8) * N + cc) =
                __floats2half2_rn((acc[mi][nj][2] + b0) * scale,
                                  (acc[mi][nj][3] + b1) * scale);
        }
    }
}

// A=half, C=f32: final output projection (A = ctx)
__global__ __launch_bounds__(256, 2) void gemm_h2f(
    const __half* __restrict__ A, const float* __restrict__ W,
    const float* __restrict__ bias, float* __restrict__ C,
    int M, int N, int K)
{
    __shared__ uint32_t As[128 * GSTR];
    __shared__ uint32_t Ws[128 * GSTR];

    const int tid = threadIdx.x;
    const int l  = tid & 31, w = tid >> 5;
    const int wm = w >> 2, wn = w & 3, lg = l >> 2, lt = l & 3;
    const int ra = tid >> 1, seg = (tid & 1) * 16;

    const __half* Ap = A + (size_t)(blockIdx.y * 128 + ra) * K + seg;
    const float*  Wp = W + (size_t)(blockIdx.x * 128 + ra) * K + seg;

    const uint32_t ash = smem_u32(As), wsh = smem_u32(Ws);
    const uint32_t a_off = ((wm * 64 + (l & 7) + ((l >> 3) & 1) * 8) * GSTR
                           + (l >> 4) * 4) * 4;
    const uint32_t b_off = ((wn * 32 + (l >> 4) * 8 + (l & 7)) * GSTR
                           + ((l >> 3) & 1) * 4) * 4;

    float acc[4][4][4];
#pragma unroll
    for (int mi = 0; mi < 4; mi++)
#pragma unroll
        for (int nj = 0; nj < 4; nj++)
#pragma unroll
            for (int r = 0; r < 4; r++) acc[mi][nj][r] = 0.0f;

    uint4 ph[2];
    float4 pb[4];
    ph[0] = *(const uint4*)(Ap);
    ph[1] = *(const uint4*)(Ap + 8);
#pragma unroll
    for (int i = 0; i < 4; i++) pb[i] = *(const float4*)(Wp + i * 4);

    const int NCH = K / 32;
    for (int c = 0; c < NCH; c++) {
        __syncthreads();
        *(uint4*)&As[ra * GSTR + (seg >> 1)]     = ph[0];
        *(uint4*)&As[ra * GSTR + (seg >> 1) + 4] = ph[1];
#pragma unroll
        for (int i = 0; i < 4; i++) {
            uint2 uw = make_uint2(h2pack(pb[i].x, pb[i].y), h2pack(pb[i].z, pb[i].w));
            *(uint2*)&Ws[ra * GSTR + (seg >> 1) + i * 2] = uw;
        }
        if (c + 1 < NCH) {
            const __half* Ap2 = Ap + (c + 1) * 32;
            const float*  Wp2 = Wp + (c + 1) * 32;
            ph[0] = *(const uint4*)(Ap2);
            ph[1] = *(const uint4*)(Ap2 + 8);
#pragma unroll
            for (int i = 0; i < 4; i++) pb[i] = *(const float4*)(Wp2 + i * 4);
        }
        __syncthreads();

#pragma unroll
        for (int ks = 0; ks < 2; ks++) {
            uint32_t af[4][4], bf[2][4];
#pragma unroll
            for (int mi = 0; mi < 4; mi++)
                ldsm4(af[mi], ash + a_off + (mi * 16 * GSTR + ks * 8) * 4);
#pragma unroll
            for (int j2 = 0; j2 < 2; j2++)
                ldsm4(bf[j2], wsh + b_off + (j2 * 16 * GSTR + ks * 8) * 4);
#pragma unroll
            for (int mi = 0; mi < 4; mi++)
#pragma unroll
                for (int nj = 0; nj < 4; nj++)
                    mma16(acc[mi][nj], af[mi], &bf[nj >> 1][(nj & 1) * 2]);
        }
    }

#pragma unroll
    for (int mi = 0; mi < 4; mi++) {
        int r = blockIdx.y * 128 + wm * 64 + mi * 16 + lg;
#pragma unroll
        for (int nj = 0; nj < 4; nj++) {
            int cc = blockIdx.x * 128 + wn * 32 + nj * 8 + lt * 2;
            float b0 = bias[cc], b1 = bias[cc + 1];
            *(float2*)(C + (size_t)r * N + cc) =
                make_float2(acc[mi][nj][0] + b0, acc[mi][nj][1] + b1);
            *(float2*)(C + (size_t)(r + 8) * N + cc) =
                make_float2(acc[mi][nj][2] + b0, acc[mi][nj][3] + b1);
        }
    }
}

// ---------------------------------------------------------------------------
// FP16 flash attention, cp.async double-buffered K/V, ldmatrix fragments,
// P kept entirely in registers (S fragment == PV A fragment).
// Q-tile 128 x K-tile 64, 256 threads, 8 warps, warp w owns rows [16w,16w+16).
// Smem (words, stride 68 == 4 mod 32): Qs 128x68 | Ks 2x64x68 | Vs 2x64x68.
// Vs holds V in natural [key][dim] layout; PV B-fragments via ldmatrix.trans.
// 2 syncthreads per iteration.
// ---------------------------------------------------------------------------
#define ASTRD 68
#define NIT   (SEQ / 64)

__global__ __launch_bounds__(256, 2) void attn_h(
    const __half* __restrict__ Q, const __half* __restrict__ K,
    const __half* __restrict__ V, __half* __restrict__ O)
{
    extern __shared__ uint32_t sm[];
    const int tid = threadIdx.x;
    const int l = tid & 31, w = tid >> 5;
    const int lg = l >> 2, lt = l & 3;
    const int b = blockIdx.x >> 4, h = blockIdx.x & 15;
    const int q0 = blockIdx.y * 128;
    const int r0 = w * 16 + lg;

    const size_t base = (size_t)b * SEQ * DMODEL + (size_t)h * HDIM;

    const uint32_t qsh = smem_u32(sm);
    const uint32_t ksh = qsh + 128 * ASTRD * 4;
    const uint32_t vsh = ksh + 2 * 64 * ASTRD * 4;

    // --- stage Q (cp.async, one group) ---
    {
        int r = tid >> 1, half64 = (tid & 1);
        const __half* qg = Q + base + (size_t)(q0 + r) * DMODEL + half64 * 64;
        uint32_t d = qsh + (r * ASTRD + half64 * 32) * 4;
#pragma unroll
        for (int i = 0; i < 8; i++)
            cpa16(d + i * 16, qg + i * 8);
        cpa_commit();
    }

    const int vr = tid >> 2, vc = (tid & 3) * 4;   // staging coords for K/V

    auto issueK = [&](int kt, int buf) {
        const __half* g = K + base + (size_t)(kt * 64 + vr) * DMODEL + vc * 8;
        uint32_t d = ksh + buf * 64 * ASTRD * 4 + (vr * ASTRD + vc * 4) * 4;
#pragma unroll
        for (int i = 0; i < 4; i++) cpa16(d + i * 16, g + i * 8);
        cpa_commit();
    };
    auto issueV = [&](int kt, int buf) {
        const __half* g = V + base + (size_t)(kt * 64 + vr) * DMODEL + vc * 8;
        uint32_t d = vsh + buf * 64 * ASTRD * 4 + (vr * ASTRD + vc * 4) * 4;
#pragma unroll
        for (int i = 0; i < 4; i++) cpa16(d + i * 16, g + i * 8);
        cpa_commit();
    };

    issueK(0, 0);
    issueV(0, 0);

    // per-lane ldmatrix address components (bytes)
    const uint32_t q_off  = ((w * 16 + (l & 7) + ((l >> 3) & 1) * 8) * ASTRD
                            + (l >> 4) * 4) * 4;
    const uint32_t k_lane = (((l >> 4) * 8 + (l & 7)) * ASTRD
                            + ((l >> 3) & 1) * 4) * 4;
    const uint32_t v_lane = ((((l >> 3) & 1) * 8 + (l & 7)) * ASTRD
                            + (l >> 4) * 4) * 4;

    float o[16][4];
#pragma unroll
    for (int j = 0; j < 16; j++)
#pragma unroll
        for (int r = 0; r < 4; r++) o[j][r] = 0.0f;
    float m_lo = -INFINITY, m_hi = -INFINITY, l_lo = 0.0f, l_hi = 0.0f;

    for (int i = 0; i < NIT; i++) {
        const int kb = i & 1;
        if (i + 1 < NIT) { issueK(i + 1, kb ^ 1); cpa_wait<2>(); }
        else             { cpa_wait<1>(); }
        __syncthreads();

        // S = Q @ K^T
        const uint32_t ksb = ksh + kb * 64 * ASTRD * 4;
        float s[8][4];
#pragma unroll
        for (int j = 0; j < 8; j++)
#pragma unroll
            for (int r = 0; r < 4; r++) s[j][r] = 0.0f;
#pragma unroll
        for (int ks = 0; ks < 8; ks++) {
            uint32_t af[4];
            ldsm4(af, qsh + q_off + ks * 32);
#pragma unroll
            for (int j2 = 0; j2 < 4; j2++) {
                uint32_t bf[4];
                ldsm4(bf, ksb + k_lane + (j2 * 16 * ASTRD) * 4 + ks * 32);
                mma16(s[2 * j2], af, bf);
                mma16(s[2 * j2 + 1], af, bf + 2);
            }
        }

        // online softmax (rows r0, r0+8); s -> p in place
        float mlo = -INFINITY, mhi = -INFINITY;
#pragma unroll
        for (int j = 0; j < 8; j++) {
            mlo = fmaxf(mlo, fmaxf(s[j][0], s[j][1]));
            mhi = fmaxf(mhi, fmaxf(s[j][2], s[j][3]));
        }
        mlo = fmaxf(mlo, __shfl_xor_sync(0xffffffffu, mlo, 1));
        mlo = fmaxf(mlo, __shfl_xor_sync(0xffffffffu, mlo, 2));
        mhi = fmaxf(mhi, __shfl_xor_sync(0xffffffffu, mhi, 1));
        mhi = fmaxf(mhi, __shfl_xor_sync(0xffffffffu, mhi, 2));
        float mnl = fmaxf(m_lo, mlo), mnh = fmaxf(m_hi, mhi);
        float al = __expf(m_lo - mnl), ah = __expf(m_hi - mnh);

        float pl = 0.0f, ph = 0.0f;
#pragma unroll
        for (int j = 0; j < 8; j++) {
            s[j][0] = __expf(s[j][0] - mnl);
            s[j][1] = __expf(s[j][1] - mnl);
            s[j][2] = __expf(s[j][2] - mnh);
            s[j][3] = __expf(s[j][3] - mnh);
            pl += s[j][0] + s[j][1];
            ph += s[j][2] + s[j][3];
        }
        pl += __shfl_xor_sync(0xffffffffu, pl, 1);
        pl += __shfl_xor_sync(0xffffffffu, pl, 2);
        ph += __shfl_xor_sync(0xffffffffu, ph, 1);
        ph += __shfl_xor_sync(0xffffffffu, ph, 2);
        l_lo = l_lo * al + pl;
        l_hi = l_hi * ah + ph;
        m_lo = mnl; m_hi = mnh;
#pragma unroll
        for (int j = 0; j < 16; j++) {
            o[j][0] *= al; o[j][1] *= al;
            o[j][2] *= ah; o[j][3] *= ah;
        }

        if (i + 1 < NIT) { issueV(i + 1, kb ^ 1); cpa_wait<2>(); }
        else             { cpa_wait<0>(); }
        __syncthreads();

        // O += P @ V   (P packed from registers; V via ldmatrix.trans)
        const uint32_t vsb = vsh + kb * 64 * ASTRD * 4;
#pragma unroll
        for (int ks = 0; ks < 4; ks++) {
            uint32_t pa[4];
            pa[0] = h2pack(s[2 * ks][0],     s[2 * ks][1]);
            pa[1] = h2pack(s[2 * ks][2],     s[2 * ks][3]);
            pa[2] = h2pack(s[2 * ks + 1][0], s[2 * ks + 1][1]);
            pa[3] = h2pack(s[2 * ks + 1][2], s[2 * ks + 1][3]);
#pragma unroll
            for (int j2 = 0; j2 < 8; j2++) {
                uint32_t bf[4];
                ldsm4t(bf, vsb + v_lane + (ks * 16 * ASTRD) * 4 + j2 * 32);
                mma16(o[2 * j2], pa, bf);
                mma16(o[2 * j2 + 1], pa, bf + 2);
            }
        }
    }

    // normalize + store (half)
    float il = 1.0f / l_lo, ih = 1.0f / l_hi;
    __half* orow0 = O + base + (size_t)(q0 + r0) * DMODEL;
    __half* orow1 = O + base + (size_t)(q0 + r0 + 8) * DMODEL;
#pragma unroll
    for (int j = 0; j < 16; j++) {
        int c = j * 8 + lt * 2;
        *(__half2*)(orow0 + c) = __floats2half2_rn(o[j][0] * il, o[j][1] * il);
        *(__half2*)(orow1 + c) = __floats2half2_rn(o[j][2] * ih, o[j][3] * ih);
    }
}

// ---------------------------------------------------------------------------
extern "C" void kernel_launch(void* const* d_in, const int* in_sizes, int n_in,
                              void* d_out, int out_size)
{
    const float* x  = (const float*)d_in[0];
    const float* Wq = (const float*)d_in[1];
    const float* bq = (const float*)d_in[2];
    const float* Wk = (const float*)d_in[3];
    const float* bk = (const float*)d_in[4];
    const float* Wv = (const float*)d_in[5];
    const float* bv = (const float*)d_in[6];
    const float* Wo = (const float*)d_in[7];
    const float* bo = (const float*)d_in[8];
    float* out = (float*)d_out;

    __half *qp, *kp, *vp, *cp;
    cudaGetSymbolAddress((void**)&qp, g_q);
    cudaGetSymbolAddress((void**)&kp, g_k);
    cudaGetSymbolAddress((void**)&vp, g_v);
    cudaGetSymbolAddress((void**)&cp, g_ctx);

    const int attn_smem = (128 * ASTRD + 2 * 64 * ASTRD + 2 * 64 * ASTRD) * 4; // 104448 B
    cudaFuncSetAttribute(attn_h, cudaFuncAttributeMaxDynamicSharedMemorySize,
                         attn_smem);

    const float qscale = 0.08838834764831845f;   // 1/sqrt(128)

    dim3 gproj(DMODEL / 128, MROWS / 128);   // (16, 64)
    gemm_f2h<<<gproj, 256>>>(x, Wq, bq, qp, qscale, MROWS, DMODEL, DMODEL);
    gemm_f2h<<<gproj, 256>>>(x, Wk, bk, kp, 1.0f,   MROWS, DMODEL, DMODEL);
    gemm_f2h<<<gproj, 256>>>(x, Wv, bv, vp, 1.0f,   MROWS, DMODEL, DMODEL);

    dim3 gattn(BATCH * NHEAD, SEQ / 128);    // (64, 16)
    attn_h<<<gattn, 256, attn_smem>>>(qp, kp, vp, cp);

    gemm_h2f<<<gproj, 256>>>(cp, Wo, bo, out, MROWS, DMODEL, DMODEL);
}

// round 10
// speedup vs baseline: 9.5543x; 1.3236x over previous
#include <cuda_runtime.h>
#include <cuda_fp16.h>
#include <math.h>
#include <stdint.h>

#define BATCH 4
#define SEQ   2048
#define DMODEL 2048
#define NHEAD 16
#define HDIM  128
#define MROWS (BATCH * SEQ)   // 8192

// Scratch (allocation-free rule: __device__ globals)
__device__ __half g_q[(size_t)MROWS * DMODEL];
__device__ __half g_k[(size_t)MROWS * DMODEL];
__device__ __half g_v[(size_t)MROWS * DMODEL];
__device__ __half g_ctx[(size_t)MROWS * DMODEL];
__device__ __half g_xh[(size_t)MROWS * DMODEL];
__device__ __half g_wqh[(size_t)DMODEL * DMODEL];
__device__ __half g_wkh[(size_t)DMODEL * DMODEL];
__device__ __half g_wvh[(size_t)DMODEL * DMODEL];
__device__ __half g_woh[(size_t)DMODEL * DMODEL];

// ---------------------------------------------------------------------------
// helpers
// ---------------------------------------------------------------------------
__device__ __forceinline__ uint32_t h2pack(float lo, float hi) {
    __half2 h = __floats2half2_rn(lo, hi);
    return *reinterpret_cast<uint32_t*>(&h);
}

__device__ __forceinline__ void mma16(float* d, const uint32_t* a, const uint32_t* b) {
    asm volatile(
        "mma.sync.aligned.m16n8k16.row.col.f32.f16.f16.f32 "
        "{%0,%1,%2,%3}, {%4,%5,%6,%7}, {%8,%9}, {%0,%1,%2,%3};\n"
        : "+f"(d[0]), "+f"(d[1]), "+f"(d[2]), "+f"(d[3])
        : "r"(a[0]), "r"(a[1]), "r"(a[2]), "r"(a[3]),
          "r"(b[0]), "r"(b[1]));
}

__device__ __forceinline__ void ldsm4(uint32_t* r, uint32_t addr) {
    asm volatile("ldmatrix.sync.aligned.m8n8.x4.shared.b16 {%0,%1,%2,%3}, [%4];"
                 : "=r"(r[0]), "=r"(r[1]), "=r"(r[2]), "=r"(r[3]) : "r"(addr));
}
__device__ __forceinline__ void ldsm4t(uint32_t* r, uint32_t addr) {
    asm volatile("ldmatrix.sync.aligned.m8n8.x4.trans.shared.b16 {%0,%1,%2,%3}, [%4];"
                 : "=r"(r[0]), "=r"(r[1]), "=r"(r[2]), "=r"(r[3]) : "r"(addr));
}

__device__ __forceinline__ void cpa16(uint32_t sa, const void* g) {
    asm volatile("cp.async.cg.shared.global [%0], [%1], 16;\n" :: "r"(sa), "l"(g));
}
__device__ __forceinline__ void cpa_commit() {
    asm volatile("cp.async.commit_group;\n");
}
template <int N>
__device__ __forceinline__ void cpa_wait() {
    asm volatile("cp.async.wait_group %0;\n" :: "n"(N));
}
__device__ __forceinline__ uint32_t smem_u32(const void* p) {
    return (uint32_t)__cvta_generic_to_shared(p);
}

// ---------------------------------------------------------------------------
// one-shot f32 -> f16 conversion (n % 4 == 0)
// ---------------------------------------------------------------------------
__global__ __launch_bounds__(256) void f2h_kernel(
    const float* __restrict__ in, __half* __restrict__ out, int n)
{
    int i = (blockIdx.x * 256 + threadIdx.x) * 4;
    if (i < n) {
        float4 v = *(const float4*)(in + i);
        uint2 u = make_uint2(h2pack(v.x, v.y), h2pack(v.z, v.w));
        *(uint2*)(out + i) = u;
    }
}

// ---------------------------------------------------------------------------
// Pure-fp16 GEMM:  C[M,N] = A[M,K] @ W[N,K]^T + bias[N]  (optional *scale)
// Block 128x128, chunk K=32, 256 thr, warps 2(m)x4(n), warp tile 64x32.
// Both operands staged via cp.async, 4-stage pipeline, ONE bar per chunk
// (issue-after-sync makes the 4-deep buffer rotation race-free).
// Smem stride 20 words: ldmatrix 8-lane phases are bank permutations.
// ---------------------------------------------------------------------------
#define GSTR  20
#define STG_W (128 * GSTR)            // words per operand per stage (2560)
#define STG_B (2 * STG_W * 4)         // bytes per stage (20480)
#define GNST  4

template <bool HALF_OUT>
__global__ __launch_bounds__(256, 2) void gemm_hh(
    const __half* __restrict__ A, const __half* __restrict__ W,
    const float* __restrict__ bias, void* __restrict__ Cv,
    float scale, int M, int N, int K)
{
    extern __shared__ uint32_t gsm[];
    const uint32_t sb = smem_u32(gsm);

    const int tid = threadIdx.x;
    const int l  = tid & 31, w = tid >> 5;
    const int wm = w >> 2, wn = w & 3, lg = l >> 2, lt = l & 3;

    const int ra   = tid >> 1;         // 0..127 staging row
    const int hseg = tid & 1;          // half-row selector (32B each)

    const __half* Ap = A + (size_t)(blockIdx.y * 128 + ra) * K + hseg * 16;
    const __half* Wp = W + (size_t)(blockIdx.x * 128 + ra) * K + hseg * 16;
    const uint32_t sdst = (ra * GSTR + hseg * 8) * 4;

    auto issue = [&](int c) {
        const uint32_t ab = sb + (c & 3) * STG_B + sdst;
        const uint32_t wb = ab + STG_W * 4;
        const __half* ag = Ap + c * 32;
        const __half* wg = Wp + c * 32;
        cpa16(ab, ag);       cpa16(ab + 16, ag + 8);
        cpa16(wb, wg);       cpa16(wb + 16, wg + 8);
        cpa_commit();
    };

    const uint32_t a_off = ((wm * 64 + (l & 7) + ((l >> 3) & 1) * 8) * GSTR
                           + (l >> 4) * 4) * 4;
    const uint32_t b_off = ((wn * 32 + (l >> 4) * 8 + (l & 7)) * GSTR
                           + ((l >> 3) & 1) * 4) * 4;

    float acc[4][4][4];
#pragma unroll
    for (int mi = 0; mi < 4; mi++)
#pragma unroll
        for (int nj = 0; nj < 4; nj++)
#pragma unroll
            for (int r = 0; r < 4; r++) acc[mi][nj][r] = 0.0f;

    const int NCH = K / 32;
    issue(0); issue(1); issue(2);

    for (int c = 0; c < NCH; c++) {
        if (c + 2 < NCH)      cpa_wait<2>();
        else if (c + 1 < NCH) cpa_wait<1>();
        else                  cpa_wait<0>();
        __syncthreads();
        if (c + 3 < NCH) issue(c + 3);

        const uint32_t ab = sb + (c & 3) * STG_B;
        const uint32_t wb = ab + STG_W * 4;
#pragma unroll
        for (int ks = 0; ks < 2; ks++) {
            uint32_t af[4][4], bf[2][4];
#pragma unroll
            for (int mi = 0; mi < 4; mi++)
                ldsm4(af[mi], ab + a_off + (mi * 16 * GSTR + ks * 8) * 4);
#pragma unroll
            for (int j2 = 0; j2 < 2; j2++)
                ldsm4(bf[j2], wb + b_off + (j2 * 16 * GSTR + ks * 8) * 4);
#pragma unroll
            for (int mi = 0; mi < 4; mi++)
#pragma unroll
                for (int nj = 0; nj < 4; nj++)
                    mma16(acc[mi][nj], af[mi], &bf[nj >> 1][(nj & 1) * 2]);
        }
    }

#pragma unroll
    for (int mi = 0; mi < 4; mi++) {
        int r = blockIdx.y * 128 + wm * 64 + mi * 16 + lg;
#pragma unroll
        for (int nj = 0; nj < 4; nj++) {
            int cc = blockIdx.x * 128 + wn * 32 + nj * 8 + lt * 2;
            float b0 = bias[cc], b1 = bias[cc + 1];
            if (HALF_OUT) {
                __half* C = (__half*)Cv;
                *(__half2*)(C + (size_t)r * N + cc) =
                    __floats2half2_rn((acc[mi][nj][0] + b0) * scale,
                                      (acc[mi][nj][1] + b1) * scale);
                *(__half2*)(C + (size_t)(r + 8) * N + cc) =
                    __floats2half2_rn((acc[mi][nj][2] + b0) * scale,
                                      (acc[mi][nj][3] + b1) * scale);
            } else {
                float* C = (float*)Cv;
                *(float2*)(C + (size_t)r * N + cc) =
                    make_float2(acc[mi][nj][0] + b0, acc[mi][nj][1] + b1);
                *(float2*)(C + (size_t)(r + 8) * N + cc) =
                    make_float2(acc[mi][nj][2] + b0, acc[mi][nj][3] + b1);
            }
        }
    }
}

// ---------------------------------------------------------------------------
// FP16 flash attention (byte-identical to round 9 — 485us, known good).
// ---------------------------------------------------------------------------
#define ASTRD 68
#define NIT   (SEQ / 64)

__global__ __launch_bounds__(256, 2) void attn_h(
    const __half* __restrict__ Q, const __half* __restrict__ K,
    const __half* __restrict__ V, __half* __restrict__ O)
{
    extern __shared__ uint32_t sm[];
    const int tid = threadIdx.x;
    const int l = tid & 31, w = tid >> 5;
    const int lg = l >> 2, lt = l & 3;
    const int b = blockIdx.x >> 4, h = blockIdx.x & 15;
    const int q0 = blockIdx.y * 128;
    const int r0 = w * 16 + lg;

    const size_t base = (size_t)b * SEQ * DMODEL + (size_t)h * HDIM;

    const uint32_t qsh = smem_u32(sm);
    const uint32_t ksh = qsh + 128 * ASTRD * 4;
    const uint32_t vsh = ksh + 2 * 64 * ASTRD * 4;

    {
        int r = tid >> 1, half64 = (tid & 1);
        const __half* qg = Q + base + (size_t)(q0 + r) * DMODEL + half64 * 64;
        uint32_t d = qsh + (r * ASTRD + half64 * 32) * 4;
#pragma unroll
        for (int i = 0; i < 8; i++)
            cpa16(d + i * 16, qg + i * 8);
        cpa_commit();
    }

    const int vr = tid >> 2, vc = (tid & 3) * 4;

    auto issueK = [&](int kt, int buf) {
        const __half* g = K + base + (size_t)(kt * 64 + vr) * DMODEL + vc * 8;
        uint32_t d = ksh + buf * 64 * ASTRD * 4 + (vr * ASTRD + vc * 4) * 4;
#pragma unroll
        for (int i = 0; i < 4; i++) cpa16(d + i * 16, g + i * 8);
        cpa_commit();
    };
    auto issueV = [&](int kt, int buf) {
        const __half* g = V + base + (size_t)(kt * 64 + vr) * DMODEL + vc * 8;
        uint32_t d = vsh + buf * 64 * ASTRD * 4 + (vr * ASTRD + vc * 4) * 4;
#pragma unroll
        for (int i = 0; i < 4; i++) cpa16(d + i * 16, g + i * 8);
        cpa_commit();
    };

    issueK(0, 0);
    issueV(0, 0);

    const uint32_t q_off  = ((w * 16 + (l & 7) + ((l >> 3) & 1) * 8) * ASTRD
                            + (l >> 4) * 4) * 4;
    const uint32_t k_lane = (((l >> 4) * 8 + (l & 7)) * ASTRD
                            + ((l >> 3) & 1) * 4) * 4;
    const uint32_t v_lane = ((((l >> 3) & 1) * 8 + (l & 7)) * ASTRD
                            + (l >> 4) * 4) * 4;

    float o[16][4];
#pragma unroll
    for (int j = 0; j < 16; j++)
#pragma unroll
        for (int r = 0; r < 4; r++) o[j][r] = 0.0f;
    float m_lo = -INFINITY, m_hi = -INFINITY, l_lo = 0.0f, l_hi = 0.0f;

    for (int i = 0; i < NIT; i++) {
        const int kb = i & 1;
        if (i + 1 < NIT) { issueK(i + 1, kb ^ 1); cpa_wait<2>(); }
        else             { cpa_wait<1>(); }
        __syncthreads();

        const uint32_t ksb = ksh + kb * 64 * ASTRD * 4;
        float s[8][4];
#pragma unroll
        for (int j = 0; j < 8; j++)
#pragma unroll
            for (int r = 0; r < 4; r++) s[j][r] = 0.0f;
#pragma unroll
        for (int ks = 0; ks < 8; ks++) {
            uint32_t af[4];
            ldsm4(af, qsh + q_off + ks * 32);
#pragma unroll
            for (int j2 = 0; j2 < 4; j2++) {
                uint32_t bf[4];
                ldsm4(bf, ksb + k_lane + (j2 * 16 * ASTRD) * 4 + ks * 32);
                mma16(s[2 * j2], af, bf);
                mma16(s[2 * j2 + 1], af, bf + 2);
            }
        }

        float mlo = -INFINITY, mhi = -INFINITY;
#pragma unroll
        for (int j = 0; j < 8; j++) {
            mlo = fmaxf(mlo, fmaxf(s[j][0], s[j][1]));
            mhi = fmaxf(mhi, fmaxf(s[j][2], s[j][3]));
        }
        mlo = fmaxf(mlo, __shfl_xor_sync(0xffffffffu, mlo, 1));
        mlo = fmaxf(mlo, __shfl_xor_sync(0xffffffffu, mlo, 2));
        mhi = fmaxf(mhi, __shfl_xor_sync(0xffffffffu, mhi, 1));
        mhi = fmaxf(mhi, __shfl_xor_sync(0xffffffffu, mhi, 2));
        float mnl = fmaxf(m_lo, mlo), mnh = fmaxf(m_hi, mhi);
        float al = __expf(m_lo - mnl), ah = __expf(m_hi - mnh);

        float pl = 0.0f, ph = 0.0f;
#pragma unroll
        for (int j = 0; j < 8; j++) {
            s[j][0] = __expf(s[j][0] - mnl);
            s[j][1] = __expf(s[j][1] - mnl);
            s[j][2] = __expf(s[j][2] - mnh);
            s[j][3] = __expf(s[j][3] - mnh);
            pl += s[j][0] + s[j][1];
            ph += s[j][2] + s[j][3];
        }
        pl += __shfl_xor_sync(0xffffffffu, pl, 1);
        pl += __shfl_xor_sync(0xffffffffu, pl, 2);
        ph += __shfl_xor_sync(0xffffffffu, ph, 1);
        ph += __shfl_xor_sync(0xffffffffu, ph, 2);
        l_lo = l_lo * al + pl;
        l_hi = l_hi * ah + ph;
        m_lo = mnl; m_hi = mnh;
#pragma unroll
        for (int j = 0; j < 16; j++) {
            o[j][0] *= al; o[j][1] *= al;
            o[j][2] *= ah; o[j][3] *= ah;
        }

        if (i + 1 < NIT) { issueV(i + 1, kb ^ 1); cpa_wait<2>(); }
        else             { cpa_wait<0>(); }
        __syncthreads();

        const uint32_t vsb = vsh + kb * 64 * ASTRD * 4;
#pragma unroll
        for (int ks = 0; ks < 4; ks++) {
            uint32_t pa[4];
            pa[0] = h2pack(s[2 * ks][0],     s[2 * ks][1]);
            pa[1] = h2pack(s[2 * ks][2],     s[2 * ks][3]);
            pa[2] = h2pack(s[2 * ks + 1][0], s[2 * ks + 1][1]);
            pa[3] = h2pack(s[2 * ks + 1][2], s[2 * ks + 1][3]);
#pragma unroll
            for (int j2 = 0; j2 < 8; j2++) {
                uint32_t bf[4];
                ldsm4t(bf, vsb + v_lane + (ks * 16 * ASTRD) * 4 + j2 * 32);
                mma16(o[2 * j2], pa, bf);
                mma16(o[2 * j2 + 1], pa, bf + 2);
            }
        }
    }

    float il = 1.0f / l_lo, ih = 1.0f / l_hi;
    __half* orow0 = O + base + (size_t)(q0 + r0) * DMODEL;
    __half* orow1 = O + base + (size_t)(q0 + r0 + 8) * DMODEL;
#pragma unroll
    for (int j = 0; j < 16; j++) {
        int c = j * 8 + lt * 2;
        *(__half2*)(orow0 + c) = __floats2half2_rn(o[j][0] * il, o[j][1] * il);
        *(__half2*)(orow1 + c) = __floats2half2_rn(o[j][2] * ih, o[j][3] * ih);
    }
}

// ---------------------------------------------------------------------------
extern "C" void kernel_launch(void* const* d_in, const int* in_sizes, int n_in,
                              void* d_out, int out_size)
{
    const float* x  = (const float*)d_in[0];
    const float* Wq = (const float*)d_in[1];
    const float* bq = (const float*)d_in[2];
    const float* Wk = (const float*)d_in[3];
    const float* bk = (const float*)d_in[4];
    const float* Wv = (const float*)d_in[5];
    const float* bv = (const float*)d_in[6];
    const float* Wo = (const float*)d_in[7];
    const float* bo = (const float*)d_in[8];
    float* out = (float*)d_out;

    __half *qp, *kp, *vp, *cp, *xh, *wqh, *wkh, *wvh, *woh;
    cudaGetSymbolAddress((void**)&qp,  g_q);
    cudaGetSymbolAddress((void**)&kp,  g_k);
    cudaGetSymbolAddress((void**)&vp,  g_v);
    cudaGetSymbolAddress((void**)&cp,  g_ctx);
    cudaGetSymbolAddress((void**)&xh,  g_xh);
    cudaGetSymbolAddress((void**)&wqh, g_wqh);
    cudaGetSymbolAddress((void**)&wkh, g_wkh);
    cudaGetSymbolAddress((void**)&wvh, g_wvh);
    cudaGetSymbolAddress((void**)&woh, g_woh);

    const int gemm_smem = GNST * STG_B;   // 81920 B
    const int attn_smem = (128 * ASTRD + 2 * 64 * ASTRD + 2 * 64 * ASTRD) * 4; // 104448 B
    cudaFuncSetAttribute(gemm_hh<true>,  cudaFuncAttributeMaxDynamicSharedMemorySize, gemm_smem);
    cudaFuncSetAttribute(gemm_hh<false>, cudaFuncAttributeMaxDynamicSharedMemorySize, gemm_smem);
    cudaFuncSetAttribute(attn_h, cudaFuncAttributeMaxDynamicSharedMemorySize, attn_smem);

    // one-shot conversions
    const int nx = MROWS * DMODEL;          // 16,777,216
    const int nw = DMODEL * DMODEL;         //  4,194,304
    f2h_kernel<<<nx / 1024, 256>>>(x,  xh,  nx);
    f2h_kernel<<<nw / 1024, 256>>>(Wq, wqh, nw);
    f2h_kernel<<<nw / 1024, 256>>>(Wk, wkh, nw);
    f2h_kernel<<<nw / 1024, 256>>>(Wv, wvh, nw);
    f2h_kernel<<<nw / 1024, 256>>>(Wo, woh, nw);

    const float qscale = 0.08838834764831845f;   // 1/sqrt(128)

    dim3 gproj(DMODEL / 128, MROWS / 128);   // (16, 64)
    gemm_hh<true><<<gproj, 256, gemm_smem>>>(xh, wqh, bq, qp, qscale, MROWS, DMODEL, DMODEL);
    gemm_hh<true><<<gproj, 256, gemm_smem>>>(xh, wkh, bk, kp, 1.0f,   MROWS, DMODEL, DMODEL);
    gemm_hh<true><<<gproj, 256, gemm_smem>>>(xh, wvh, bv, vp, 1.0f,   MROWS, DMODEL, DMODEL);

    dim3 gattn(BATCH * NHEAD, SEQ / 128);    // (64, 16)
    attn_h<<<gattn, 256, attn_smem>>>(qp, kp, vp, cp);

    gemm_hh<false><<<gproj, 256, gemm_smem>>>(cp, woh, bo, out, 1.0f, MROWS, DMODEL, DMODEL);
}